// round 13
// baseline (speedup 1.0000x reference)
#include <cuda_runtime.h>
#include <cuda_bf16.h>
#include <cstdint>

#define BB 2
#define SS 2048
#define DIM 2048
#define NH 16
#define HD 128
#define RANK 32
#define MROWS (BB*SS)
#define DD ((size_t)DIM*DIM)

// -------- scratch (device globals; no allocation allowed) --------
__device__ __nv_bfloat16 g_xh [MROWS*DIM];
__device__ __nv_bfloat16 g_xl [MROWS*DIM];
__device__ __nv_bfloat16 g_aoh[MROWS*DIM];
__device__ __nv_bfloat16 g_aol[MROWS*DIM];
__device__ __nv_bfloat16 g_wh [4][DIM*DIM];
__device__ __nv_bfloat16 g_wl [4][DIM*DIM];
__device__ __nv_bfloat16 g_qbh[MROWS*DIM];
__device__ __nv_bfloat16 g_qbl[MROWS*DIM];
__device__ __nv_bfloat16 g_kbh[MROWS*DIM];
__device__ __nv_bfloat16 g_kbl[MROWS*DIM];
__device__ __nv_bfloat16 g_vbh[MROWS*DIM];
__device__ __nv_bfloat16 g_vbl[MROWS*DIM];
__device__ __nv_bfloat16 g_qhh[MROWS*RANK];
__device__ __nv_bfloat16 g_qhl[MROWS*RANK];
__device__ __nv_bfloat16 g_khh[MROWS*RANK];
__device__ __nv_bfloat16 g_khl[MROWS*RANK];

__device__ __forceinline__ uint32_t smem_to_u32(const void* smem_ptr) {
    uint32_t addr;
    asm("{ .reg .u64 tmp; cvta.to.shared.u64 tmp, %1; cvt.u32.u64 %0, tmp; }"
        : "=r"(addr) : "l"(smem_ptr));
    return addr;
}
__device__ __forceinline__ void ldsm_x4(uint32_t& d0, uint32_t& d1, uint32_t& d2,
                                        uint32_t& d3, uint32_t addr) {
    asm volatile("ldmatrix.sync.aligned.m8n8.x4.shared.b16 {%0,%1,%2,%3}, [%4];"
                 : "=r"(d0), "=r"(d1), "=r"(d2), "=r"(d3) : "r"(addr));
}
__device__ __forceinline__ void ldsm_x4t(uint32_t& d0, uint32_t& d1, uint32_t& d2,
                                         uint32_t& d3, uint32_t addr) {
    asm volatile("ldmatrix.sync.aligned.m8n8.x4.trans.shared.b16 {%0,%1,%2,%3}, [%4];"
                 : "=r"(d0), "=r"(d1), "=r"(d2), "=r"(d3) : "r"(addr));
}
__device__ __forceinline__ void mma_bf16(float* c, const uint32_t* a,
                                         uint32_t b0, uint32_t b1) {
    asm volatile("mma.sync.aligned.m16n8k16.row.col.f32.bf16.bf16.f32 "
                 "{%0,%1,%2,%3}, {%4,%5,%6,%7}, {%8,%9}, {%0,%1,%2,%3};"
                 : "+f"(c[0]), "+f"(c[1]), "+f"(c[2]), "+f"(c[3])
                 : "r"(a[0]), "r"(a[1]), "r"(a[2]), "r"(a[3]), "r"(b0), "r"(b1));
}
__device__ __forceinline__ void cp16(uint32_t dst, const void* src) {
    asm volatile("cp.async.cg.shared.global [%0], [%1], 16;" :: "r"(dst), "l"(src));
}
#define CP_COMMIT()  asm volatile("cp.async.commit_group;" ::: "memory")
#define CP_WAIT(n)   asm volatile("cp.async.wait_group %0;" :: "n"(n) : "memory")

__device__ __forceinline__ float fast_rcp(float x) {
    float r; asm("rcp.approx.f32 %0, %1;" : "=f"(r) : "f"(x)); return r;
}
__device__ __forceinline__ float fast_ex2(float x) {
    float r; asm("ex2.approx.f32 %0, %1;" : "=f"(r) : "f"(x)); return r;
}

__device__ __forceinline__ void split2(float x, float y, uint32_t& hi, uint32_t& lo) {
    __nv_bfloat16 hx = __float2bfloat16(x), hy = __float2bfloat16(y);
    float rx = x - __bfloat162float(hx), ry = y - __bfloat162float(hy);
    __nv_bfloat162 H; H.x = hx; H.y = hy;
    __nv_bfloat162 L; L.x = __float2bfloat16(rx); L.y = __float2bfloat16(ry);
    hi = *(uint32_t*)&H; lo = *(uint32_t*)&L;
}

// ============================================================
// fp32 -> (bf16 hi, bf16 lo)
// ============================================================
__global__ __launch_bounds__(256) void f32_to_bf16pair(const float* __restrict__ in,
                                                       __nv_bfloat16* __restrict__ hi,
                                                       __nv_bfloat16* __restrict__ lo) {
    int i = blockIdx.x * 256 + threadIdx.x;
    float4 v = ((const float4*)in)[i];
    __nv_bfloat162 h0, h1, l0, l1;
    h0.x = __float2bfloat16(v.x); h0.y = __float2bfloat16(v.y);
    h1.x = __float2bfloat16(v.z); h1.y = __float2bfloat16(v.w);
    l0.x = __float2bfloat16(v.x - __bfloat162float(h0.x));
    l0.y = __float2bfloat16(v.y - __bfloat162float(h0.y));
    l1.x = __float2bfloat16(v.z - __bfloat162float(h1.x));
    l1.y = __float2bfloat16(v.w - __bfloat162float(h1.y));
    ((__nv_bfloat162*)hi)[2 * i]     = h0;
    ((__nv_bfloat162*)hi)[2 * i + 1] = h1;
    ((__nv_bfloat162*)lo)[2 * i]     = l0;
    ((__nv_bfloat162*)lo)[2 * i + 1] = l1;
}

// all 4 weights in one launch (gridDim.y = 4)
__global__ __launch_bounds__(256) void conv_w4(const float* __restrict__ w0,
                                               const float* __restrict__ w1,
                                               const float* __restrict__ w2,
                                               const float* __restrict__ w3,
                                               __nv_bfloat16* __restrict__ hi,
                                               __nv_bfloat16* __restrict__ lo) {
    int z = blockIdx.y;
    const float* in = (z == 0) ? w0 : (z == 1) ? w1 : (z == 2) ? w2 : w3;
    size_t off = (size_t)z * DD;
    int i = blockIdx.x * 256 + threadIdx.x;
    float4 v = ((const float4*)in)[i];
    __nv_bfloat162 h0, h1, l0, l1;
    h0.x = __float2bfloat16(v.x); h0.y = __float2bfloat16(v.y);
    h1.x = __float2bfloat16(v.z); h1.y = __float2bfloat16(v.w);
    l0.x = __float2bfloat16(v.x - __bfloat162float(h0.x));
    l0.y = __float2bfloat16(v.y - __bfloat162float(h0.y));
    l1.x = __float2bfloat16(v.z - __bfloat162float(h1.x));
    l1.y = __float2bfloat16(v.w - __bfloat162float(h1.y));
    ((__nv_bfloat162*)(hi + off))[2 * i]     = h0;
    ((__nv_bfloat162*)(hi + off))[2 * i + 1] = h1;
    ((__nv_bfloat162*)(lo + off))[2 * i]     = l0;
    ((__nv_bfloat162*)(lo + off))[2 * i + 1] = l1;
}

// ============================================================
// mma.sync GEMM: C = (Ahi+Alo)(Bhi+Blo)^T, dual-mode epilogue,
// 4-stage cp.async pipeline (1 CTA/SM, reg-limited)
// ============================================================
#define KDIM 2048
#define TBK 32
#define NKIT (KDIM / TBK)
#define LDK 40
#define TILE_B (128 * LDK * 2)
#define STAGE_B (4 * TILE_B)
#define NSTG 4
#define TC_SMEM (NSTG * STAGE_B)

__global__ __launch_bounds__(256) void tc_gemm(const __nv_bfloat16* __restrict__ Ahi,
                                               const __nv_bfloat16* __restrict__ Alo,
                                               const __nv_bfloat16* __restrict__ Bhi,
                                               const __nv_bfloat16* __restrict__ Blo,
                                               float* __restrict__ C,
                                               __nv_bfloat16* __restrict__ Chi,
                                               __nv_bfloat16* __restrict__ Clo,
                                               int N) {
    extern __shared__ char smem[];
    const uint32_t sb = smem_to_u32(smem);
    const int tid = threadIdx.x;
    const int wid = tid >> 5, lane = tid & 31;
    const int m0 = blockIdx.y * 128;
    const int n0 = blockIdx.x * 128;
    const int wm = (wid & 3) * 32;
    const int wn = (wid >> 2) * 64;

    const __nv_bfloat16* srcs[4] = {
        Ahi + (size_t)m0 * KDIM, Alo + (size_t)m0 * KDIM,
        Bhi + (size_t)n0 * KDIM, Blo + (size_t)n0 * KDIM };

    int l_tile[8], l_r[8], l_c[8];
#pragma unroll
    for (int u = 0; u < 8; u++) {
        int cid = u * 256 + tid;
        l_tile[u] = cid >> 9;
        int w = cid & 511;
        l_r[u] = w >> 2;
        l_c[u] = w & 3;
    }

    auto issue_stage = [&](int it, int stage) {
        uint32_t base = sb + stage * STAGE_B;
        int k0 = it * TBK;
#pragma unroll
        for (int u = 0; u < 8; u++) {
            uint32_t dst = base + l_tile[u] * TILE_B + l_r[u] * (LDK * 2) + l_c[u] * 16;
            const __nv_bfloat16* src = srcs[l_tile[u]] + (size_t)l_r[u] * KDIM + k0 + l_c[u] * 8;
            cp16(dst, src);
        }
        CP_COMMIT();
    };

    float acc[2][8][4];
#pragma unroll
    for (int i = 0; i < 2; i++)
#pragma unroll
        for (int j = 0; j < 8; j++)
#pragma unroll
            for (int q = 0; q < 4; q++) acc[i][j][q] = 0.f;

    const int lrow = lane & 15;
    const int lcol = (lane >> 4) * 8;

    issue_stage(0, 0);
    issue_stage(1, 1);
    issue_stage(2, 2);

    for (int it = 0; it < NKIT; it++) {
        if (it + 3 < NKIT) {
            issue_stage(it + 3, (it + 3) & (NSTG - 1));
        } else {
            CP_COMMIT();  // empty group keeps the wait-count exact
        }
        CP_WAIT(3);
        __syncthreads();

        uint32_t base = sb + (it & (NSTG - 1)) * STAGE_B;
        uint32_t aA_hi = base + 0 * TILE_B;
        uint32_t aA_lo = base + 1 * TILE_B;
        uint32_t aB_hi = base + 2 * TILE_B;
        uint32_t aB_lo = base + 3 * TILE_B;

#pragma unroll
        for (int ks = 0; ks < 2; ks++) {
            const int kc = ks * 16 + lcol;
            uint32_t ah[2][4], al[2][4], bh[4][4], bl[4][4];
#pragma unroll
            for (int ma = 0; ma < 2; ma++) {
                uint32_t off = (wm + ma * 16 + lrow) * (LDK * 2) + kc * 2;
                ldsm_x4(ah[ma][0], ah[ma][1], ah[ma][2], ah[ma][3], aA_hi + off);
                ldsm_x4(al[ma][0], al[ma][1], al[ma][2], al[ma][3], aA_lo + off);
            }
#pragma unroll
            for (int nb = 0; nb < 4; nb++) {
                uint32_t off = (wn + nb * 16 + lrow) * (LDK * 2) + kc * 2;
                ldsm_x4(bh[nb][0], bh[nb][1], bh[nb][2], bh[nb][3], aB_hi + off);
                ldsm_x4(bl[nb][0], bl[nb][1], bl[nb][2], bl[nb][3], aB_lo + off);
            }
#pragma unroll
            for (int ma = 0; ma < 2; ma++)
#pragma unroll
                for (int nb = 0; nb < 4; nb++) {
                    mma_bf16(acc[ma][nb * 2],     ah[ma], bh[nb][0], bh[nb][2]);
                    mma_bf16(acc[ma][nb * 2 + 1], ah[ma], bh[nb][1], bh[nb][3]);
                    mma_bf16(acc[ma][nb * 2],     ah[ma], bl[nb][0], bl[nb][2]);
                    mma_bf16(acc[ma][nb * 2 + 1], ah[ma], bl[nb][1], bl[nb][3]);
                    mma_bf16(acc[ma][nb * 2],     al[ma], bh[nb][0], bh[nb][2]);
                    mma_bf16(acc[ma][nb * 2 + 1], al[ma], bh[nb][1], bh[nb][3]);
                }
        }
        __syncthreads();
    }

    const int er = lane >> 2;
    const int ec = (lane & 3) * 2;
    if (C) {
#pragma unroll
        for (int ma = 0; ma < 2; ma++)
#pragma unroll
            for (int na = 0; na < 8; na++) {
                int row = m0 + wm + ma * 16 + er;
                int col = n0 + wn + na * 8 + ec;
                float* p0 = C + (size_t)row * N + col;
                float* p1 = C + (size_t)(row + 8) * N + col;
                p0[0] = acc[ma][na][0]; p0[1] = acc[ma][na][1];
                p1[0] = acc[ma][na][2]; p1[1] = acc[ma][na][3];
            }
    } else {
#pragma unroll
        for (int ma = 0; ma < 2; ma++)
#pragma unroll
            for (int na = 0; na < 8; na++) {
                int row = m0 + wm + ma * 16 + er;
                int col = n0 + wn + na * 8 + ec;
                size_t i0 = (size_t)row * N + col;
                size_t i1 = (size_t)(row + 8) * N + col;
                uint32_t h, l;
                split2(acc[ma][na][0], acc[ma][na][1], h, l);
                *(uint32_t*)(Chi + i0) = h; *(uint32_t*)(Clo + i0) = l;
                split2(acc[ma][na][2], acc[ma][na][3], h, l);
                *(uint32_t*)(Chi + i1) = h; *(uint32_t*)(Clo + i1) = l;
            }
    }
}

// ============================================================
// LoRA projection: 32-row blocks, both heads in one launch (y=2),
// float4 global loads
// ============================================================
__global__ __launch_bounds__(256) void lora_gemm(const float* __restrict__ X,
                                                 const float* __restrict__ Wq,
                                                 const float* __restrict__ Wk,
                                                 __nv_bfloat16* __restrict__ Qh,
                                                 __nv_bfloat16* __restrict__ Ql,
                                                 __nv_bfloat16* __restrict__ Kh,
                                                 __nv_bfloat16* __restrict__ Kl) {
    __shared__ float xs[32][33];
    __shared__ float ws[32][33];
    const float* W = blockIdx.y ? Wk : Wq;
    __nv_bfloat16* Ch = blockIdx.y ? Kh : Qh;
    __nv_bfloat16* Cl = blockIdx.y ? Kl : Ql;
    const int tid = threadIdx.x;
    const int lane = tid & 31, wrp = tid >> 5;  // 8 warps x 4 rows
    const int m0 = blockIdx.x * 32;
    const int vr = tid >> 3, vc = (tid & 7) * 4;
    float acc[4] = {0.f, 0.f, 0.f, 0.f};

    for (int k0 = 0; k0 < DIM; k0 += 32) {
        __syncthreads();
        {
            float4 xv = *(const float4*)&X[(size_t)(m0 + vr) * DIM + k0 + vc];
            xs[vr][vc] = xv.x; xs[vr][vc + 1] = xv.y;
            xs[vr][vc + 2] = xv.z; xs[vr][vc + 3] = xv.w;
            float4 wv4 = *(const float4*)&W[(size_t)vr * DIM + k0 + vc];
            ws[vr][vc] = wv4.x; ws[vr][vc + 1] = wv4.y;
            ws[vr][vc + 2] = wv4.z; ws[vr][vc + 3] = wv4.w;
        }
        __syncthreads();
#pragma unroll
        for (int kk = 0; kk < 32; kk++) {
            float wv = ws[lane][kk];
#pragma unroll
            for (int i = 0; i < 4; i++)
                acc[i] = fmaf(xs[wrp * 4 + i][kk], wv, acc[i]);
        }
    }
#pragma unroll
    for (int i = 0; i < 4; i++) {
        size_t idx = (size_t)(m0 + wrp * 4 + i) * RANK + lane;
        __nv_bfloat16 hv = __float2bfloat16(acc[i]);
        Ch[idx] = hv;
        Cl[idx] = __float2bfloat16(acc[i] - __bfloat162float(hv));
    }
}

// ============================================================
// RoPE in-place on bf16 hi/lo pairs of q and k
// ============================================================
__global__ __launch_bounds__(256) void rope_pair(__nv_bfloat16* __restrict__ qh,
                                                 __nv_bfloat16* __restrict__ ql,
                                                 __nv_bfloat16* __restrict__ kh,
                                                 __nv_bfloat16* __restrict__ kl,
                                                 const float* __restrict__ cs,
                                                 const float* __restrict__ sn) {
    int t = blockIdx.x * 256 + threadIdx.x;
    int p = t & 63;
    int row = t / (DIM / 2);
    int sidx = row & (SS - 1);
    float c = cs[sidx * 64 + p];
    float si = sn[sidx * 64 + p];

    {
        __nv_bfloat162 H = ((__nv_bfloat162*)qh)[t];
        __nv_bfloat162 L = ((__nv_bfloat162*)ql)[t];
        float x = __bfloat162float(H.x) + __bfloat162float(L.x);
        float y = __bfloat162float(H.y) + __bfloat162float(L.y);
        float ox = x * c - y * si;
        float oy = x * si + y * c;
        uint32_t hv, lv;
        split2(ox, oy, hv, lv);
        ((uint32_t*)qh)[t] = hv;
        ((uint32_t*)ql)[t] = lv;
    }
    {
        __nv_bfloat162 H = ((__nv_bfloat162*)kh)[t];
        __nv_bfloat162 L = ((__nv_bfloat162*)kl)[t];
        float x = __bfloat162float(H.x) + __bfloat162float(L.x);
        float y = __bfloat162float(H.y) + __bfloat162float(L.y);
        float ox = x * c - y * si;
        float oy = x * si + y * c;
        uint32_t hv, lv;
        split2(ox, oy, hv, lv);
        ((uint32_t*)kh)[t] = hv;
        ((uint32_t*)kl)[t] = lv;
    }
}

// ============================================================
// Tensor-core flash attention (unchanged from R12 winner)
// ============================================================
#define SQB 272
#define SRB 80
#define KTILE 17408
#define KSTG  (2 * KTILE)
#define HTILE 5120
#define HSTG  (2 * HTILE)
#define oQh 0
#define oQl 34816
#define oK  69632
#define oV  139264
#define oqh 174080
#define oql 184320
#define okh 194560
#define FSMEM 215040

__global__ __launch_bounds__(256) void flash_tc(
    const __nv_bfloat16* __restrict__ Qh_, const __nv_bfloat16* __restrict__ Ql_,
    const __nv_bfloat16* __restrict__ Kh_, const __nv_bfloat16* __restrict__ Kl_,
    const __nv_bfloat16* __restrict__ Vh_, const __nv_bfloat16* __restrict__ Vl_,
    const __nv_bfloat16* __restrict__ QHh_, const __nv_bfloat16* __restrict__ QHl_,
    const __nv_bfloat16* __restrict__ KHh_, const __nv_bfloat16* __restrict__ KHl_,
    __nv_bfloat16* __restrict__ Oh, __nv_bfloat16* __restrict__ Ol) {
    extern __shared__ char sm[];
    const uint32_t sb = smem_to_u32(sm);
    const int tid = threadIdx.x, lane = tid & 31, wid = tid >> 5;
    const int qt = gridDim.x - 1 - blockIdx.x;
    const int b = blockIdx.y >> 4, h = blockIdx.y & 15;
    const int q0 = qt * 128;
    const size_t rowbase = (size_t)b * SS;
    const int wm = wid * 16;
    const int lrow = lane & 15, lcol = (lane >> 4) * 8;
    const float SC2 = 0.08838834764831845f * 1.4426950408889634f;
    const float L2E = 1.4426950408889634f;

    auto issue_K = [&](int kt) {
        int nk0 = min(kt * 64, SS - 64);
        int stg = kt & 1;
        uint32_t bKh = sb + oK + stg * KSTG;
        uint32_t bKl = bKh + KTILE;
#pragma unroll
        for (int u = 0; u < 4; u++) {
            int cid = u * 256 + tid;
            int row = cid >> 4, col = cid & 15;
            size_t g = (rowbase + nk0 + row) * DIM + h * HD + col * 8;
            cp16(bKh + row * SQB + col * 16, Kh_ + g);
            cp16(bKl + row * SQB + col * 16, Kl_ + g);
        }
        uint32_t bkh = sb + okh + stg * HSTG;
        {
            int row = tid >> 2, col = tid & 3;
            size_t g = (rowbase + nk0 + row) * RANK + col * 8;
            cp16(bkh + row * SRB + col * 16, KHh_ + g);
            cp16(bkh + HTILE + row * SRB + col * 16, KHl_ + g);
        }
        CP_COMMIT();
    };
    auto issue_V = [&](int kt) {
        int nk0 = min(kt * 64, SS - 64);
#pragma unroll
        for (int u = 0; u < 4; u++) {
            int cid = u * 256 + tid;
            int row = cid >> 4, col = cid & 15;
            size_t g = (rowbase + nk0 + row) * DIM + h * HD + col * 8;
            cp16(sb + oV + row * SQB + col * 16, Vh_ + g);
            cp16(sb + oV + KTILE + row * SQB + col * 16, Vl_ + g);
        }
        CP_COMMIT();
    };

    // ---- prologue: Q + qh (group1), K0 (group2), V0 (group3) ----
    {
#pragma unroll
        for (int u = 0; u < 8; u++) {
            int cid = u * 256 + tid;
            int row = cid >> 4, col = cid & 15;
            size_t g = (rowbase + q0 + row) * DIM + h * HD + col * 8;
            cp16(sb + oQh + row * SQB + col * 16, Qh_ + g);
            cp16(sb + oQl + row * SQB + col * 16, Ql_ + g);
        }
#pragma unroll
        for (int u = 0; u < 2; u++) {
            int cid = u * 256 + tid;
            int row = cid >> 2, col = cid & 3;
            size_t g = (rowbase + q0 + row) * RANK + col * 8;
            cp16(sb + oqh + row * SRB + col * 16, QHh_ + g);
            cp16(sb + oql + row * SRB + col * 16, QHl_ + g);
        }
        CP_COMMIT();
    }
    issue_K(0);
    issue_V(0);

    // ---- peel: wait for Q group only, hoist Q/qh fragments to regs ----
    uint32_t qf[8][2][4];
    uint32_t qhf[2][2][4];
    CP_WAIT(2);
    __syncthreads();
#pragma unroll
    for (int ks = 0; ks < 8; ks++) {
        const int kc = ks * 16 + lcol;
        uint32_t off = (wm + lrow) * SQB + kc * 2;
        ldsm_x4(qf[ks][0][0], qf[ks][0][1], qf[ks][0][2], qf[ks][0][3], sb + oQh + off);
        ldsm_x4(qf[ks][1][0], qf[ks][1][1], qf[ks][1][2], qf[ks][1][3], sb + oQl + off);
    }
#pragma unroll
    for (int ks = 0; ks < 2; ks++) {
        const int kc = ks * 16 + lcol;
        uint32_t off = (wm + lrow) * SRB + kc * 2;
        ldsm_x4(qhf[ks][0][0], qhf[ks][0][1], qhf[ks][0][2], qhf[ks][0][3], sb + oqh + off);
        ldsm_x4(qhf[ks][1][0], qhf[ks][1][1], qhf[ks][1][2], qhf[ks][1][3], sb + oql + off);
    }

    float o[16][4];
#pragma unroll
    for (int i = 0; i < 16; i++)
#pragma unroll
        for (int e = 0; e < 4; e++) o[i][e] = 0.f;
    float m0 = -1e30f, m1 = -1e30f, l0 = 0.f, l1 = 0.f;

    const int nkt = q0 / 64 + 2;
    for (int kt = 0; kt < nkt; kt++) {
        const int k0 = kt * 64;
        const int kb = kt & 1;
        CP_WAIT(1);
        __syncthreads();
        issue_K(kt + 1);

        const bool skip = (k0 > q0 + wm + 15);
        float s[8][4];
        if (!skip) {
            const uint32_t bKh = sb + oK + kb * KSTG, bKl = bKh + KTILE;
            const uint32_t bkh = sb + okh + kb * HSTG, bkl = bkh + HTILE;

            float gg[8][4];
#pragma unroll
            for (int i = 0; i < 8; i++)
#pragma unroll
                for (int e = 0; e < 4; e++) gg[i][e] = 0.f;
#pragma unroll
            for (int ks = 0; ks < 2; ks++) {
#pragma unroll
                for (int nb = 0; nb < 4; nb++) {
                    uint32_t bh[4], bl[4];
                    uint32_t boff = (nb * 16 + lrow) * SRB + (ks * 16 + lcol) * 2;
                    ldsm_x4(bh[0], bh[1], bh[2], bh[3], bkh + boff);
                    ldsm_x4(bl[0], bl[1], bl[2], bl[3], bkl + boff);
                    mma_bf16(gg[nb * 2],     qhf[ks][0], bh[0], bh[2]);
                    mma_bf16(gg[nb * 2],     qhf[ks][0], bl[0], bl[2]);
                    mma_bf16(gg[nb * 2],     qhf[ks][1], bh[0], bh[2]);
                    mma_bf16(gg[nb * 2 + 1], qhf[ks][0], bh[1], bh[3]);
                    mma_bf16(gg[nb * 2 + 1], qhf[ks][0], bl[1], bl[3]);
                    mma_bf16(gg[nb * 2 + 1], qhf[ks][1], bh[1], bh[3]);
                }
            }
#pragma unroll
            for (int i = 0; i < 8; i++)
#pragma unroll
                for (int e = 0; e < 4; e++)
                    gg[i][e] = fast_rcp(1.f + fast_ex2(-L2E * gg[i][e]));

#pragma unroll
            for (int i = 0; i < 8; i++)
#pragma unroll
                for (int e = 0; e < 4; e++) s[i][e] = 0.f;
#pragma unroll
            for (int ks = 0; ks < 8; ks++) {
#pragma unroll
                for (int nb = 0; nb < 4; nb++) {
                    uint32_t bh[4], bl[4];
                    uint32_t boff = (nb * 16 + lrow) * SQB + (ks * 16 + lcol) * 2;
                    ldsm_x4(bh[0], bh[1], bh[2], bh[3], bKh + boff);
                    ldsm_x4(bl[0], bl[1], bl[2], bl[3], bKl + boff);
                    mma_bf16(s[nb * 2],     qf[ks][0], bh[0], bh[2]);
                    mma_bf16(s[nb * 2],     qf[ks][0], bl[0], bl[2]);
                    mma_bf16(s[nb * 2],     qf[ks][1], bh[0], bh[2]);
                    mma_bf16(s[nb * 2 + 1], qf[ks][0], bh[1], bh[3]);
                    mma_bf16(s[nb * 2 + 1], qf[ks][0], bl[1], bl[3]);
                    mma_bf16(s[nb * 2 + 1], qf[ks][1], bh[1], bh[3]);
                }
            }

            const int r0g = q0 + wm + (lane >> 2);
            if (k0 + 64 > q0 + wm) {
#pragma unroll
                for (int na = 0; na < 8; na++)
#pragma unroll
                    for (int e = 0; e < 4; e++) {
                        int key = k0 + na * 8 + (lane & 3) * 2 + (e & 1);
                        int row = r0g + (e >> 1) * 8;
                        s[na][e] = (key <= row) ? s[na][e] * SC2 : -1e30f;
                    }
            } else {
#pragma unroll
                for (int na = 0; na < 8; na++)
#pragma unroll
                    for (int e = 0; e < 4; e++) s[na][e] *= SC2;
            }

            float mx0 = -1e30f, mx1 = -1e30f;
#pragma unroll
            for (int na = 0; na < 8; na++) {
                mx0 = fmaxf(mx0, fmaxf(s[na][0], s[na][1]));
                mx1 = fmaxf(mx1, fmaxf(s[na][2], s[na][3]));
            }
            mx0 = fmaxf(mx0, __shfl_xor_sync(0xffffffffu, mx0, 1));
            mx0 = fmaxf(mx0, __shfl_xor_sync(0xffffffffu, mx0, 2));
            mx1 = fmaxf(mx1, __shfl_xor_sync(0xffffffffu, mx1, 1));
            mx1 = fmaxf(mx1, __shfl_xor_sync(0xffffffffu, mx1, 2));
            float mn0 = fmaxf(m0, mx0), mn1 = fmaxf(m1, mx1);
            float al0 = fast_ex2(m0 - mn0), al1 = fast_ex2(m1 - mn1);
            m0 = mn0; m1 = mn1;
            float rs0 = 0.f, rs1 = 0.f;
#pragma unroll
            for (int na = 0; na < 8; na++) {
                s[na][0] = fast_ex2(s[na][0] - m0); rs0 += s[na][0];
                s[na][1] = fast_ex2(s[na][1] - m0); rs0 += s[na][1];
                s[na][2] = fast_ex2(s[na][2] - m1); rs1 += s[na][2];
                s[na][3] = fast_ex2(s[na][3] - m1); rs1 += s[na][3];
            }
            rs0 += __shfl_xor_sync(0xffffffffu, rs0, 1);
            rs0 += __shfl_xor_sync(0xffffffffu, rs0, 2);
            rs1 += __shfl_xor_sync(0xffffffffu, rs1, 1);
            rs1 += __shfl_xor_sync(0xffffffffu, rs1, 2);
            l0 = l0 * al0 + rs0;
            l1 = l1 * al1 + rs1;
            if (al0 != 1.f || al1 != 1.f) {
#pragma unroll
                for (int na = 0; na < 16; na++) {
                    o[na][0] *= al0; o[na][1] *= al0;
                    o[na][2] *= al1; o[na][3] *= al1;
                }
            }
#pragma unroll
            for (int na = 0; na < 8; na++)
#pragma unroll
                for (int e = 0; e < 4; e++) s[na][e] *= gg[na][e];
        }

        CP_WAIT(1);
        __syncthreads();

        if (!skip) {
#pragma unroll
            for (int j = 0; j < 4; j++) {
                uint32_t wa[4], wl[4];
                split2(s[2 * j][0],     s[2 * j][1],     wa[0], wl[0]);
                split2(s[2 * j][2],     s[2 * j][3],     wa[1], wl[1]);
                split2(s[2 * j + 1][0], s[2 * j + 1][1], wa[2], wl[2]);
                split2(s[2 * j + 1][2], s[2 * j + 1][3], wa[3], wl[3]);
#pragma unroll
                for (int dp = 0; dp < 8; dp++) {
                    uint32_t vh[4], vl[4];
                    uint32_t voff = (j * 16 + lrow) * SQB + (dp * 16 + lcol) * 2;
                    ldsm_x4t(vh[0], vh[1], vh[2], vh[3], sb + oV + voff);
                    ldsm_x4t(vl[0], vl[1], vl[2], vl[3], sb + oV + KTILE + voff);
                    mma_bf16(o[dp * 2],     wa, vh[0], vh[1]);
                    mma_bf16(o[dp * 2],     wa, vl[0], vl[1]);
                    mma_bf16(o[dp * 2],     wl, vh[0], vh[1]);
                    mma_bf16(o[dp * 2 + 1], wa, vh[2], vh[3]);
                    mma_bf16(o[dp * 2 + 1], wa, vl[2], vl[3]);
                    mma_bf16(o[dp * 2 + 1], wl, vh[2], vh[3]);
                }
            }
        }
        __syncthreads();
        issue_V(kt + 1);
    }

    // ---- epilogue: normalized bf16 hi/lo pairs ----
    const float inv0 = fast_rcp(l0), inv1 = fast_rcp(l1);
    const int row0 = q0 + wm + (lane >> 2);
    size_t base0 = (rowbase + row0) * DIM + h * HD;
    size_t base1 = base0 + 8 * (size_t)DIM;
#pragma unroll
    for (int na = 0; na < 16; na++) {
        int d = na * 8 + (lane & 3) * 2;
        uint32_t hv, lv;
        split2(o[na][0] * inv0, o[na][1] * inv0, hv, lv);
        *(uint32_t*)(Oh + base0 + d) = hv;
        *(uint32_t*)(Ol + base0 + d) = lv;
        split2(o[na][2] * inv1, o[na][3] * inv1, hv, lv);
        *(uint32_t*)(Oh + base1 + d) = hv;
        *(uint32_t*)(Ol + base1 + d) = lv;
    }
}

// ============================================================
// launch
// ============================================================
extern "C" void kernel_launch(void* const* d_in, const int* in_sizes, int n_in,
                              void* d_out, int out_size) {
    const float* x    = (const float*)d_in[0];
    const float* fcos = (const float*)d_in[2];
    const float* fsin = (const float*)d_in[3];
    const float* wq   = (const float*)d_in[4];
    const float* wk   = (const float*)d_in[5];
    const float* wv   = (const float*)d_in[6];
    const float* wo   = (const float*)d_in[7];
    const float* waq  = (const float*)d_in[8];
    const float* wak  = (const float*)d_in[9];
    float* out = (float*)d_out;

    __nv_bfloat16 *gxh, *gxl, *gaoh, *gaol, *gwh, *gwl;
    __nv_bfloat16 *qbh, *qbl, *kbh, *kbl, *vbh, *vbl, *qhh, *qhl, *khh, *khl;
    cudaGetSymbolAddress((void**)&gxh, g_xh);
    cudaGetSymbolAddress((void**)&gxl, g_xl);
    cudaGetSymbolAddress((void**)&gaoh, g_aoh);
    cudaGetSymbolAddress((void**)&gaol, g_aol);
    cudaGetSymbolAddress((void**)&gwh, g_wh);
    cudaGetSymbolAddress((void**)&gwl, g_wl);
    cudaGetSymbolAddress((void**)&qbh, g_qbh);
    cudaGetSymbolAddress((void**)&qbl, g_qbl);
    cudaGetSymbolAddress((void**)&kbh, g_kbh);
    cudaGetSymbolAddress((void**)&kbl, g_kbl);
    cudaGetSymbolAddress((void**)&vbh, g_vbh);
    cudaGetSymbolAddress((void**)&vbl, g_vbl);
    cudaGetSymbolAddress((void**)&qhh, g_qhh);
    cudaGetSymbolAddress((void**)&qhl, g_qhl);
    cudaGetSymbolAddress((void**)&khh, g_khh);
    cudaGetSymbolAddress((void**)&khl, g_khl);

    cudaFuncSetAttribute(tc_gemm, cudaFuncAttributeMaxDynamicSharedMemorySize, TC_SMEM);
    cudaFuncSetAttribute(flash_tc, cudaFuncAttributeMaxDynamicSharedMemorySize, FSMEM);

    const int XB = MROWS * DIM / 4 / 256;
    const int WB = DIM * DIM / 4 / 256;

    f32_to_bf16pair<<<XB, 256>>>(x, gxh, gxl);
    conv_w4<<<dim3(WB, 4), 256>>>(wq, wk, wv, wo, gwh, gwl);

    dim3 gg(DIM / 128, MROWS / 128);
    tc_gemm<<<gg, 256, TC_SMEM>>>(gxh, gxl, gwh + 0 * DD, gwl + 0 * DD, nullptr, qbh, qbl, DIM);
    tc_gemm<<<gg, 256, TC_SMEM>>>(gxh, gxl, gwh + 1 * DD, gwl + 1 * DD, nullptr, kbh, kbl, DIM);
    tc_gemm<<<gg, 256, TC_SMEM>>>(gxh, gxl, gwh + 2 * DD, gwl + 2 * DD, nullptr, vbh, vbl, DIM);
    lora_gemm<<<dim3(MROWS / 32, 2), 256>>>(x, waq, wak, qhh, qhl, khh, khl);

    rope_pair<<<MROWS * (DIM / 2) / 256, 256>>>(qbh, qbl, kbh, kbl, fcos, fsin);

    flash_tc<<<dim3(SS / 128, BB * NH), 256, FSMEM>>>(qbh, qbl, kbh, kbl, vbh, vbl,
                                                      qhh, qhl, khh, khl, gaoh, gaol);

    tc_gemm<<<gg, 256, TC_SMEM>>>(gaoh, gaol, gwh + 3 * DD, gwl + 3 * DD, out, nullptr, nullptr, DIM);
}

// round 14
// speedup vs baseline: 1.1138x; 1.1138x over previous
#include <cuda_runtime.h>
#include <cuda_bf16.h>
#include <cstdint>

#define BB 2
#define SS 2048
#define DIM 2048
#define NH 16
#define HD 128
#define RANK 32
#define MROWS (BB*SS)
#define DD ((size_t)DIM*DIM)

// -------- scratch (device globals; no allocation allowed) --------
__device__ __nv_bfloat16 g_xh [MROWS*DIM];
__device__ __nv_bfloat16 g_xl [MROWS*DIM];
__device__ __nv_bfloat16 g_aoh[MROWS*DIM];
__device__ __nv_bfloat16 g_aol[MROWS*DIM];
__device__ __nv_bfloat16 g_wh [4][DIM*DIM];
__device__ __nv_bfloat16 g_wl [4][DIM*DIM];
__device__ __nv_bfloat16 g_qbh[MROWS*DIM];
__device__ __nv_bfloat16 g_qbl[MROWS*DIM];
__device__ __nv_bfloat16 g_kbh[MROWS*DIM];
__device__ __nv_bfloat16 g_kbl[MROWS*DIM];
__device__ __nv_bfloat16 g_vbh[MROWS*DIM];
__device__ __nv_bfloat16 g_vbl[MROWS*DIM];
__device__ __nv_bfloat16 g_qhh[MROWS*RANK];
__device__ __nv_bfloat16 g_qhl[MROWS*RANK];
__device__ __nv_bfloat16 g_khh[MROWS*RANK];
__device__ __nv_bfloat16 g_khl[MROWS*RANK];

__device__ __forceinline__ uint32_t smem_to_u32(const void* smem_ptr) {
    uint32_t addr;
    asm("{ .reg .u64 tmp; cvta.to.shared.u64 tmp, %1; cvt.u32.u64 %0, tmp; }"
        : "=r"(addr) : "l"(smem_ptr));
    return addr;
}
__device__ __forceinline__ void ldsm_x4(uint32_t& d0, uint32_t& d1, uint32_t& d2,
                                        uint32_t& d3, uint32_t addr) {
    asm volatile("ldmatrix.sync.aligned.m8n8.x4.shared.b16 {%0,%1,%2,%3}, [%4];"
                 : "=r"(d0), "=r"(d1), "=r"(d2), "=r"(d3) : "r"(addr));
}
__device__ __forceinline__ void ldsm_x4t(uint32_t& d0, uint32_t& d1, uint32_t& d2,
                                         uint32_t& d3, uint32_t addr) {
    asm volatile("ldmatrix.sync.aligned.m8n8.x4.trans.shared.b16 {%0,%1,%2,%3}, [%4];"
                 : "=r"(d0), "=r"(d1), "=r"(d2), "=r"(d3) : "r"(addr));
}
__device__ __forceinline__ void mma_bf16(float* c, const uint32_t* a,
                                         uint32_t b0, uint32_t b1) {
    asm volatile("mma.sync.aligned.m16n8k16.row.col.f32.bf16.bf16.f32 "
                 "{%0,%1,%2,%3}, {%4,%5,%6,%7}, {%8,%9}, {%0,%1,%2,%3};"
                 : "+f"(c[0]), "+f"(c[1]), "+f"(c[2]), "+f"(c[3])
                 : "r"(a[0]), "r"(a[1]), "r"(a[2]), "r"(a[3]), "r"(b0), "r"(b1));
}
__device__ __forceinline__ void cp16(uint32_t dst, const void* src) {
    asm volatile("cp.async.cg.shared.global [%0], [%1], 16;" :: "r"(dst), "l"(src));
}
#define CP_COMMIT()  asm volatile("cp.async.commit_group;" ::: "memory")
#define CP_WAIT(n)   asm volatile("cp.async.wait_group %0;" :: "n"(n) : "memory")

__device__ __forceinline__ float fast_rcp(float x) {
    float r; asm("rcp.approx.f32 %0, %1;" : "=f"(r) : "f"(x)); return r;
}
__device__ __forceinline__ float fast_ex2(float x) {
    float r; asm("ex2.approx.f32 %0, %1;" : "=f"(r) : "f"(x)); return r;
}

__device__ __forceinline__ void split2(float x, float y, uint32_t& hi, uint32_t& lo) {
    __nv_bfloat16 hx = __float2bfloat16(x), hy = __float2bfloat16(y);
    float rx = x - __bfloat162float(hx), ry = y - __bfloat162float(hy);
    __nv_bfloat162 H; H.x = hx; H.y = hy;
    __nv_bfloat162 L; L.x = __float2bfloat16(rx); L.y = __float2bfloat16(ry);
    hi = *(uint32_t*)&H; lo = *(uint32_t*)&L;
}

// ============================================================
// fp32 -> (bf16 hi, bf16 lo)
// ============================================================
__global__ __launch_bounds__(256) void f32_to_bf16pair(const float* __restrict__ in,
                                                       __nv_bfloat16* __restrict__ hi,
                                                       __nv_bfloat16* __restrict__ lo) {
    int i = blockIdx.x * 256 + threadIdx.x;
    float4 v = ((const float4*)in)[i];
    __nv_bfloat162 h0, h1, l0, l1;
    h0.x = __float2bfloat16(v.x); h0.y = __float2bfloat16(v.y);
    h1.x = __float2bfloat16(v.z); h1.y = __float2bfloat16(v.w);
    l0.x = __float2bfloat16(v.x - __bfloat162float(h0.x));
    l0.y = __float2bfloat16(v.y - __bfloat162float(h0.y));
    l1.x = __float2bfloat16(v.z - __bfloat162float(h1.x));
    l1.y = __float2bfloat16(v.w - __bfloat162float(h1.y));
    ((__nv_bfloat162*)hi)[2 * i]     = h0;
    ((__nv_bfloat162*)hi)[2 * i + 1] = h1;
    ((__nv_bfloat162*)lo)[2 * i]     = l0;
    ((__nv_bfloat162*)lo)[2 * i + 1] = l1;
}

// all 4 weights in one launch (gridDim.y = 4)
__global__ __launch_bounds__(256) void conv_w4(const float* __restrict__ w0,
                                               const float* __restrict__ w1,
                                               const float* __restrict__ w2,
                                               const float* __restrict__ w3,
                                               __nv_bfloat16* __restrict__ hi,
                                               __nv_bfloat16* __restrict__ lo) {
    int z = blockIdx.y;
    const float* in = (z == 0) ? w0 : (z == 1) ? w1 : (z == 2) ? w2 : w3;
    size_t off = (size_t)z * DD;
    int i = blockIdx.x * 256 + threadIdx.x;
    float4 v = ((const float4*)in)[i];
    __nv_bfloat162 h0, h1, l0, l1;
    h0.x = __float2bfloat16(v.x); h0.y = __float2bfloat16(v.y);
    h1.x = __float2bfloat16(v.z); h1.y = __float2bfloat16(v.w);
    l0.x = __float2bfloat16(v.x - __bfloat162float(h0.x));
    l0.y = __float2bfloat16(v.y - __bfloat162float(h0.y));
    l1.x = __float2bfloat16(v.z - __bfloat162float(h1.x));
    l1.y = __float2bfloat16(v.w - __bfloat162float(h1.y));
    ((__nv_bfloat162*)(hi + off))[2 * i]     = h0;
    ((__nv_bfloat162*)(hi + off))[2 * i + 1] = h1;
    ((__nv_bfloat162*)(lo + off))[2 * i]     = l0;
    ((__nv_bfloat162*)(lo + off))[2 * i + 1] = l1;
}

// ============================================================
// mma.sync GEMM: C = (Ahi+Alo)(Bhi+Blo)^T
// 2-stage pipeline, pinned to 2 CTAs/SM (<=128 regs, 80KB smem).
// Epilogue modes: f32 out | bf16 pair out | bf16 pair + fused RoPE.
// ============================================================
#define KDIM 2048
#define TBK 32
#define NKIT (KDIM / TBK)
#define LDK 40
#define TILE_B (128 * LDK * 2)
#define STAGE_B (4 * TILE_B)
#define TC_SMEM (2 * STAGE_B)

__global__ __launch_bounds__(256, 2) void tc_gemm(const __nv_bfloat16* __restrict__ Ahi,
                                                  const __nv_bfloat16* __restrict__ Alo,
                                                  const __nv_bfloat16* __restrict__ Bhi,
                                                  const __nv_bfloat16* __restrict__ Blo,
                                                  float* __restrict__ C,
                                                  __nv_bfloat16* __restrict__ Chi,
                                                  __nv_bfloat16* __restrict__ Clo,
                                                  const float* __restrict__ cs,
                                                  const float* __restrict__ sn,
                                                  int N) {
    extern __shared__ char smem[];
    const uint32_t sb = smem_to_u32(smem);
    const int tid = threadIdx.x;
    const int wid = tid >> 5, lane = tid & 31;
    const int m0 = blockIdx.y * 128;
    const int n0 = blockIdx.x * 128;
    const int wm = (wid & 3) * 32;
    const int wn = (wid >> 2) * 64;

    const __nv_bfloat16* srcs[4] = {
        Ahi + (size_t)m0 * KDIM, Alo + (size_t)m0 * KDIM,
        Bhi + (size_t)n0 * KDIM, Blo + (size_t)n0 * KDIM };

    int l_tile[8], l_r[8], l_c[8];
#pragma unroll
    for (int u = 0; u < 8; u++) {
        int cid = u * 256 + tid;
        l_tile[u] = cid >> 9;
        int w = cid & 511;
        l_r[u] = w >> 2;
        l_c[u] = w & 3;
    }

    auto issue_stage = [&](int it, int stage) {
        uint32_t base = sb + stage * STAGE_B;
        int k0 = it * TBK;
#pragma unroll
        for (int u = 0; u < 8; u++) {
            uint32_t dst = base + l_tile[u] * TILE_B + l_r[u] * (LDK * 2) + l_c[u] * 16;
            const __nv_bfloat16* src = srcs[l_tile[u]] + (size_t)l_r[u] * KDIM + k0 + l_c[u] * 8;
            cp16(dst, src);
        }
        CP_COMMIT();
    };

    float acc[2][8][4];
#pragma unroll
    for (int i = 0; i < 2; i++)
#pragma unroll
        for (int j = 0; j < 8; j++)
#pragma unroll
            for (int q = 0; q < 4; q++) acc[i][j][q] = 0.f;

    const int lrow = lane & 15;
    const int lcol = (lane >> 4) * 8;

    issue_stage(0, 0);

    for (int it = 0; it < NKIT; it++) {
        int cur = it & 1;
        if (it + 1 < NKIT) {
            issue_stage(it + 1, cur ^ 1);
            CP_WAIT(1);
        } else {
            CP_WAIT(0);
        }
        __syncthreads();

        uint32_t base = sb + cur * STAGE_B;
        uint32_t aA_hi = base + 0 * TILE_B;
        uint32_t aA_lo = base + 1 * TILE_B;
        uint32_t aB_hi = base + 2 * TILE_B;
        uint32_t aB_lo = base + 3 * TILE_B;

#pragma unroll
        for (int ks = 0; ks < 2; ks++) {
            const int kc = ks * 16 + lcol;
            uint32_t ah[2][4], al[2][4], bh[4][4], bl[4][4];
#pragma unroll
            for (int ma = 0; ma < 2; ma++) {
                uint32_t off = (wm + ma * 16 + lrow) * (LDK * 2) + kc * 2;
                ldsm_x4(ah[ma][0], ah[ma][1], ah[ma][2], ah[ma][3], aA_hi + off);
                ldsm_x4(al[ma][0], al[ma][1], al[ma][2], al[ma][3], aA_lo + off);
            }
#pragma unroll
            for (int nb = 0; nb < 4; nb++) {
                uint32_t off = (wn + nb * 16 + lrow) * (LDK * 2) + kc * 2;
                ldsm_x4(bh[nb][0], bh[nb][1], bh[nb][2], bh[nb][3], aB_hi + off);
                ldsm_x4(bl[nb][0], bl[nb][1], bl[nb][2], bl[nb][3], aB_lo + off);
            }
#pragma unroll
            for (int ma = 0; ma < 2; ma++)
#pragma unroll
                for (int nb = 0; nb < 4; nb++) {
                    mma_bf16(acc[ma][nb * 2],     ah[ma], bh[nb][0], bh[nb][2]);
                    mma_bf16(acc[ma][nb * 2 + 1], ah[ma], bh[nb][1], bh[nb][3]);
                    mma_bf16(acc[ma][nb * 2],     ah[ma], bl[nb][0], bl[nb][2]);
                    mma_bf16(acc[ma][nb * 2 + 1], ah[ma], bl[nb][1], bl[nb][3]);
                    mma_bf16(acc[ma][nb * 2],     al[ma], bh[nb][0], bh[nb][2]);
                    mma_bf16(acc[ma][nb * 2 + 1], al[ma], bh[nb][1], bh[nb][3]);
                }
        }
        __syncthreads();
    }

    const int er = lane >> 2;
    const int ec = (lane & 3) * 2;
    if (C) {
#pragma unroll
        for (int ma = 0; ma < 2; ma++)
#pragma unroll
            for (int na = 0; na < 8; na++) {
                int row = m0 + wm + ma * 16 + er;
                int col = n0 + wn + na * 8 + ec;
                float* p0 = C + (size_t)row * N + col;
                float* p1 = C + (size_t)(row + 8) * N + col;
                p0[0] = acc[ma][na][0]; p0[1] = acc[ma][na][1];
                p1[0] = acc[ma][na][2]; p1[1] = acc[ma][na][3];
            }
    } else {
#pragma unroll
        for (int ma = 0; ma < 2; ma++)
#pragma unroll
            for (int na = 0; na < 8; na++) {
                int row = m0 + wm + ma * 16 + er;
                int col = n0 + wn + na * 8 + ec;
                float a0 = acc[ma][na][0], a1 = acc[ma][na][1];
                float a2 = acc[ma][na][2], a3 = acc[ma][na][3];
                if (cs) {   // fused RoPE: (a0,a1) and (a2,a3) are (even,odd) pairs
                    int p = (col & 127) >> 1;
                    int s0 = row & (SS - 1), s1 = (row + 8) & (SS - 1);
                    float c0 = cs[s0 * 64 + p], v0 = sn[s0 * 64 + p];
                    float c1 = cs[s1 * 64 + p], v1 = sn[s1 * 64 + p];
                    float t;
                    t = a0 * c0 - a1 * v0; a1 = a0 * v0 + a1 * c0; a0 = t;
                    t = a2 * c1 - a3 * v1; a3 = a2 * v1 + a3 * c1; a2 = t;
                }
                size_t i0 = (size_t)row * N + col;
                size_t i1 = (size_t)(row + 8) * N + col;
                uint32_t h, l;
                split2(a0, a1, h, l);
                *(uint32_t*)(Chi + i0) = h; *(uint32_t*)(Clo + i0) = l;
                split2(a2, a3, h, l);
                *(uint32_t*)(Chi + i1) = h; *(uint32_t*)(Clo + i1) = l;
            }
    }
}

// ============================================================
// LoRA projection: 32-row blocks, both heads in one launch (y=2),
// float4 global loads
// ============================================================
__global__ __launch_bounds__(256) void lora_gemm(const float* __restrict__ X,
                                                 const float* __restrict__ Wq,
                                                 const float* __restrict__ Wk,
                                                 __nv_bfloat16* __restrict__ Qh,
                                                 __nv_bfloat16* __restrict__ Ql,
                                                 __nv_bfloat16* __restrict__ Kh,
                                                 __nv_bfloat16* __restrict__ Kl) {
    __shared__ float xs[32][33];
    __shared__ float ws[32][33];
    const float* W = blockIdx.y ? Wk : Wq;
    __nv_bfloat16* Ch = blockIdx.y ? Kh : Qh;
    __nv_bfloat16* Cl = blockIdx.y ? Kl : Ql;
    const int tid = threadIdx.x;
    const int lane = tid & 31, wrp = tid >> 5;
    const int m0 = blockIdx.x * 32;
    const int vr = tid >> 3, vc = (tid & 7) * 4;
    float acc[4] = {0.f, 0.f, 0.f, 0.f};

    for (int k0 = 0; k0 < DIM; k0 += 32) {
        __syncthreads();
        {
            float4 xv = *(const float4*)&X[(size_t)(m0 + vr) * DIM + k0 + vc];
            xs[vr][vc] = xv.x; xs[vr][vc + 1] = xv.y;
            xs[vr][vc + 2] = xv.z; xs[vr][vc + 3] = xv.w;
            float4 wv4 = *(const float4*)&W[(size_t)vr * DIM + k0 + vc];
            ws[vr][vc] = wv4.x; ws[vr][vc + 1] = wv4.y;
            ws[vr][vc + 2] = wv4.z; ws[vr][vc + 3] = wv4.w;
        }
        __syncthreads();
#pragma unroll
        for (int kk = 0; kk < 32; kk++) {
            float wv = ws[lane][kk];
#pragma unroll
            for (int i = 0; i < 4; i++)
                acc[i] = fmaf(xs[wrp * 4 + i][kk], wv, acc[i]);
        }
    }
#pragma unroll
    for (int i = 0; i < 4; i++) {
        size_t idx = (size_t)(m0 + wrp * 4 + i) * RANK + lane;
        __nv_bfloat16 hv = __float2bfloat16(acc[i]);
        Ch[idx] = hv;
        Cl[idx] = __float2bfloat16(acc[i] - __bfloat162float(hv));
    }
}

// ============================================================
// Tensor-core flash attention (R12 winner, unchanged)
// ============================================================
#define SQB 272
#define SRB 80
#define KTILE 17408
#define KSTG  (2 * KTILE)
#define HTILE 5120
#define HSTG  (2 * HTILE)
#define oQh 0
#define oQl 34816
#define oK  69632
#define oV  139264
#define oqh 174080
#define oql 184320
#define okh 194560
#define FSMEM 215040

__global__ __launch_bounds__(256) void flash_tc(
    const __nv_bfloat16* __restrict__ Qh_, const __nv_bfloat16* __restrict__ Ql_,
    const __nv_bfloat16* __restrict__ Kh_, const __nv_bfloat16* __restrict__ Kl_,
    const __nv_bfloat16* __restrict__ Vh_, const __nv_bfloat16* __restrict__ Vl_,
    const __nv_bfloat16* __restrict__ QHh_, const __nv_bfloat16* __restrict__ QHl_,
    const __nv_bfloat16* __restrict__ KHh_, const __nv_bfloat16* __restrict__ KHl_,
    __nv_bfloat16* __restrict__ Oh, __nv_bfloat16* __restrict__ Ol) {
    extern __shared__ char sm[];
    const uint32_t sb = smem_to_u32(sm);
    const int tid = threadIdx.x, lane = tid & 31, wid = tid >> 5;
    const int qt = gridDim.x - 1 - blockIdx.x;
    const int b = blockIdx.y >> 4, h = blockIdx.y & 15;
    const int q0 = qt * 128;
    const size_t rowbase = (size_t)b * SS;
    const int wm = wid * 16;
    const int lrow = lane & 15, lcol = (lane >> 4) * 8;
    const float SC2 = 0.08838834764831845f * 1.4426950408889634f;
    const float L2E = 1.4426950408889634f;

    auto issue_K = [&](int kt) {
        int nk0 = min(kt * 64, SS - 64);
        int stg = kt & 1;
        uint32_t bKh = sb + oK + stg * KSTG;
        uint32_t bKl = bKh + KTILE;
#pragma unroll
        for (int u = 0; u < 4; u++) {
            int cid = u * 256 + tid;
            int row = cid >> 4, col = cid & 15;
            size_t g = (rowbase + nk0 + row) * DIM + h * HD + col * 8;
            cp16(bKh + row * SQB + col * 16, Kh_ + g);
            cp16(bKl + row * SQB + col * 16, Kl_ + g);
        }
        uint32_t bkh = sb + okh + stg * HSTG;
        {
            int row = tid >> 2, col = tid & 3;
            size_t g = (rowbase + nk0 + row) * RANK + col * 8;
            cp16(bkh + row * SRB + col * 16, KHh_ + g);
            cp16(bkh + HTILE + row * SRB + col * 16, KHl_ + g);
        }
        CP_COMMIT();
    };
    auto issue_V = [&](int kt) {
        int nk0 = min(kt * 64, SS - 64);
#pragma unroll
        for (int u = 0; u < 4; u++) {
            int cid = u * 256 + tid;
            int row = cid >> 4, col = cid & 15;
            size_t g = (rowbase + nk0 + row) * DIM + h * HD + col * 8;
            cp16(sb + oV + row * SQB + col * 16, Vh_ + g);
            cp16(sb + oV + KTILE + row * SQB + col * 16, Vl_ + g);
        }
        CP_COMMIT();
    };

    {
#pragma unroll
        for (int u = 0; u < 8; u++) {
            int cid = u * 256 + tid;
            int row = cid >> 4, col = cid & 15;
            size_t g = (rowbase + q0 + row) * DIM + h * HD + col * 8;
            cp16(sb + oQh + row * SQB + col * 16, Qh_ + g);
            cp16(sb + oQl + row * SQB + col * 16, Ql_ + g);
        }
#pragma unroll
        for (int u = 0; u < 2; u++) {
            int cid = u * 256 + tid;
            int row = cid >> 2, col = cid & 3;
            size_t g = (rowbase + q0 + row) * RANK + col * 8;
            cp16(sb + oqh + row * SRB + col * 16, QHh_ + g);
            cp16(sb + oql + row * SRB + col * 16, QHl_ + g);
        }
        CP_COMMIT();
    }
    issue_K(0);
    issue_V(0);

    uint32_t qf[8][2][4];
    uint32_t qhf[2][2][4];
    CP_WAIT(2);
    __syncthreads();
#pragma unroll
    for (int ks = 0; ks < 8; ks++) {
        const int kc = ks * 16 + lcol;
        uint32_t off = (wm + lrow) * SQB + kc * 2;
        ldsm_x4(qf[ks][0][0], qf[ks][0][1], qf[ks][0][2], qf[ks][0][3], sb + oQh + off);
        ldsm_x4(qf[ks][1][0], qf[ks][1][1], qf[ks][1][2], qf[ks][1][3], sb + oQl + off);
    }
#pragma unroll
    for (int ks = 0; ks < 2; ks++) {
        const int kc = ks * 16 + lcol;
        uint32_t off = (wm + lrow) * SRB + kc * 2;
        ldsm_x4(qhf[ks][0][0], qhf[ks][0][1], qhf[ks][0][2], qhf[ks][0][3], sb + oqh + off);
        ldsm_x4(qhf[ks][1][0], qhf[ks][1][1], qhf[ks][1][2], qhf[ks][1][3], sb + oql + off);
    }

    float o[16][4];
#pragma unroll
    for (int i = 0; i < 16; i++)
#pragma unroll
        for (int e = 0; e < 4; e++) o[i][e] = 0.f;
    float m0 = -1e30f, m1 = -1e30f, l0 = 0.f, l1 = 0.f;

    const int nkt = q0 / 64 + 2;
    for (int kt = 0; kt < nkt; kt++) {
        const int k0 = kt * 64;
        const int kb = kt & 1;
        CP_WAIT(1);
        __syncthreads();
        issue_K(kt + 1);

        const bool skip = (k0 > q0 + wm + 15);
        float s[8][4];
        if (!skip) {
            const uint32_t bKh = sb + oK + kb * KSTG, bKl = bKh + KTILE;
            const uint32_t bkh = sb + okh + kb * HSTG, bkl = bkh + HTILE;

            float gg[8][4];
#pragma unroll
            for (int i = 0; i < 8; i++)
#pragma unroll
                for (int e = 0; e < 4; e++) gg[i][e] = 0.f;
#pragma unroll
            for (int ks = 0; ks < 2; ks++) {
#pragma unroll
                for (int nb = 0; nb < 4; nb++) {
                    uint32_t bh[4], bl[4];
                    uint32_t boff = (nb * 16 + lrow) * SRB + (ks * 16 + lcol) * 2;
                    ldsm_x4(bh[0], bh[1], bh[2], bh[3], bkh + boff);
                    ldsm_x4(bl[0], bl[1], bl[2], bl[3], bkl + boff);
                    mma_bf16(gg[nb * 2],     qhf[ks][0], bh[0], bh[2]);
                    mma_bf16(gg[nb * 2],     qhf[ks][0], bl[0], bl[2]);
                    mma_bf16(gg[nb * 2],     qhf[ks][1], bh[0], bh[2]);
                    mma_bf16(gg[nb * 2 + 1], qhf[ks][0], bh[1], bh[3]);
                    mma_bf16(gg[nb * 2 + 1], qhf[ks][0], bl[1], bl[3]);
                    mma_bf16(gg[nb * 2 + 1], qhf[ks][1], bh[1], bh[3]);
                }
            }
#pragma unroll
            for (int i = 0; i < 8; i++)
#pragma unroll
                for (int e = 0; e < 4; e++)
                    gg[i][e] = fast_rcp(1.f + fast_ex2(-L2E * gg[i][e]));

#pragma unroll
            for (int i = 0; i < 8; i++)
#pragma unroll
                for (int e = 0; e < 4; e++) s[i][e] = 0.f;
#pragma unroll
            for (int ks = 0; ks < 8; ks++) {
#pragma unroll
                for (int nb = 0; nb < 4; nb++) {
                    uint32_t bh[4], bl[4];
                    uint32_t boff = (nb * 16 + lrow) * SQB + (ks * 16 + lcol) * 2;
                    ldsm_x4(bh[0], bh[1], bh[2], bh[3], bKh + boff);
                    ldsm_x4(bl[0], bl[1], bl[2], bl[3], bKl + boff);
                    mma_bf16(s[nb * 2],     qf[ks][0], bh[0], bh[2]);
                    mma_bf16(s[nb * 2],     qf[ks][0], bl[0], bl[2]);
                    mma_bf16(s[nb * 2],     qf[ks][1], bh[0], bh[2]);
                    mma_bf16(s[nb * 2 + 1], qf[ks][0], bh[1], bh[3]);
                    mma_bf16(s[nb * 2 + 1], qf[ks][0], bl[1], bl[3]);
                    mma_bf16(s[nb * 2 + 1], qf[ks][1], bh[1], bh[3]);
                }
            }

            const int r0g = q0 + wm + (lane >> 2);
            if (k0 + 64 > q0 + wm) {
#pragma unroll
                for (int na = 0; na < 8; na++)
#pragma unroll
                    for (int e = 0; e < 4; e++) {
                        int key = k0 + na * 8 + (lane & 3) * 2 + (e & 1);
                        int row = r0g + (e >> 1) * 8;
                        s[na][e] = (key <= row) ? s[na][e] * SC2 : -1e30f;
                    }
            } else {
#pragma unroll
                for (int na = 0; na < 8; na++)
#pragma unroll
                    for (int e = 0; e < 4; e++) s[na][e] *= SC2;
            }

            float mx0 = -1e30f, mx1 = -1e30f;
#pragma unroll
            for (int na = 0; na < 8; na++) {
                mx0 = fmaxf(mx0, fmaxf(s[na][0], s[na][1]));
                mx1 = fmaxf(mx1, fmaxf(s[na][2], s[na][3]));
            }
            mx0 = fmaxf(mx0, __shfl_xor_sync(0xffffffffu, mx0, 1));
            mx0 = fmaxf(mx0, __shfl_xor_sync(0xffffffffu, mx0, 2));
            mx1 = fmaxf(mx1, __shfl_xor_sync(0xffffffffu, mx1, 1));
            mx1 = fmaxf(mx1, __shfl_xor_sync(0xffffffffu, mx1, 2));
            float mn0 = fmaxf(m0, mx0), mn1 = fmaxf(m1, mx1);
            float al0 = fast_ex2(m0 - mn0), al1 = fast_ex2(m1 - mn1);
            m0 = mn0; m1 = mn1;
            float rs0 = 0.f, rs1 = 0.f;
#pragma unroll
            for (int na = 0; na < 8; na++) {
                s[na][0] = fast_ex2(s[na][0] - m0); rs0 += s[na][0];
                s[na][1] = fast_ex2(s[na][1] - m0); rs0 += s[na][1];
                s[na][2] = fast_ex2(s[na][2] - m1); rs1 += s[na][2];
                s[na][3] = fast_ex2(s[na][3] - m1); rs1 += s[na][3];
            }
            rs0 += __shfl_xor_sync(0xffffffffu, rs0, 1);
            rs0 += __shfl_xor_sync(0xffffffffu, rs0, 2);
            rs1 += __shfl_xor_sync(0xffffffffu, rs1, 1);
            rs1 += __shfl_xor_sync(0xffffffffu, rs1, 2);
            l0 = l0 * al0 + rs0;
            l1 = l1 * al1 + rs1;
            if (al0 != 1.f || al1 != 1.f) {
#pragma unroll
                for (int na = 0; na < 16; na++) {
                    o[na][0] *= al0; o[na][1] *= al0;
                    o[na][2] *= al1; o[na][3] *= al1;
                }
            }
#pragma unroll
            for (int na = 0; na < 8; na++)
#pragma unroll
                for (int e = 0; e < 4; e++) s[na][e] *= gg[na][e];
        }

        CP_WAIT(1);
        __syncthreads();

        if (!skip) {
#pragma unroll
            for (int j = 0; j < 4; j++) {
                uint32_t wa[4], wl[4];
                split2(s[2 * j][0],     s[2 * j][1],     wa[0], wl[0]);
                split2(s[2 * j][2],     s[2 * j][3],     wa[1], wl[1]);
                split2(s[2 * j + 1][0], s[2 * j + 1][1], wa[2], wl[2]);
                split2(s[2 * j + 1][2], s[2 * j + 1][3], wa[3], wl[3]);
#pragma unroll
                for (int dp = 0; dp < 8; dp++) {
                    uint32_t vh[4], vl[4];
                    uint32_t voff = (j * 16 + lrow) * SQB + (dp * 16 + lcol) * 2;
                    ldsm_x4t(vh[0], vh[1], vh[2], vh[3], sb + oV + voff);
                    ldsm_x4t(vl[0], vl[1], vl[2], vl[3], sb + oV + KTILE + voff);
                    mma_bf16(o[dp * 2],     wa, vh[0], vh[1]);
                    mma_bf16(o[dp * 2],     wa, vl[0], vl[1]);
                    mma_bf16(o[dp * 2],     wl, vh[0], vh[1]);
                    mma_bf16(o[dp * 2 + 1], wa, vh[2], vh[3]);
                    mma_bf16(o[dp * 2 + 1], wa, vl[2], vl[3]);
                    mma_bf16(o[dp * 2 + 1], wl, vh[2], vh[3]);
                }
            }
        }
        __syncthreads();
        issue_V(kt + 1);
    }

    const float inv0 = fast_rcp(l0), inv1 = fast_rcp(l1);
    const int row0 = q0 + wm + (lane >> 2);
    size_t base0 = (rowbase + row0) * DIM + h * HD;
    size_t base1 = base0 + 8 * (size_t)DIM;
#pragma unroll
    for (int na = 0; na < 16; na++) {
        int d = na * 8 + (lane & 3) * 2;
        uint32_t hv, lv;
        split2(o[na][0] * inv0, o[na][1] * inv0, hv, lv);
        *(uint32_t*)(Oh + base0 + d) = hv;
        *(uint32_t*)(Ol + base0 + d) = lv;
        split2(o[na][2] * inv1, o[na][3] * inv1, hv, lv);
        *(uint32_t*)(Oh + base1 + d) = hv;
        *(uint32_t*)(Ol + base1 + d) = lv;
    }
}

// ============================================================
// launch
// ============================================================
extern "C" void kernel_launch(void* const* d_in, const int* in_sizes, int n_in,
                              void* d_out, int out_size) {
    const float* x    = (const float*)d_in[0];
    const float* fcos = (const float*)d_in[2];
    const float* fsin = (const float*)d_in[3];
    const float* wq   = (const float*)d_in[4];
    const float* wk   = (const float*)d_in[5];
    const float* wv   = (const float*)d_in[6];
    const float* wo   = (const float*)d_in[7];
    const float* waq  = (const float*)d_in[8];
    const float* wak  = (const float*)d_in[9];
    float* out = (float*)d_out;

    __nv_bfloat16 *gxh, *gxl, *gaoh, *gaol, *gwh, *gwl;
    __nv_bfloat16 *qbh, *qbl, *kbh, *kbl, *vbh, *vbl, *qhh, *qhl, *khh, *khl;
    cudaGetSymbolAddress((void**)&gxh, g_xh);
    cudaGetSymbolAddress((void**)&gxl, g_xl);
    cudaGetSymbolAddress((void**)&gaoh, g_aoh);
    cudaGetSymbolAddress((void**)&gaol, g_aol);
    cudaGetSymbolAddress((void**)&gwh, g_wh);
    cudaGetSymbolAddress((void**)&gwl, g_wl);
    cudaGetSymbolAddress((void**)&qbh, g_qbh);
    cudaGetSymbolAddress((void**)&qbl, g_qbl);
    cudaGetSymbolAddress((void**)&kbh, g_kbh);
    cudaGetSymbolAddress((void**)&kbl, g_kbl);
    cudaGetSymbolAddress((void**)&vbh, g_vbh);
    cudaGetSymbolAddress((void**)&vbl, g_vbl);
    cudaGetSymbolAddress((void**)&qhh, g_qhh);
    cudaGetSymbolAddress((void**)&qhl, g_qhl);
    cudaGetSymbolAddress((void**)&khh, g_khh);
    cudaGetSymbolAddress((void**)&khl, g_khl);

    cudaFuncSetAttribute(tc_gemm, cudaFuncAttributeMaxDynamicSharedMemorySize, TC_SMEM);
    cudaFuncSetAttribute(flash_tc, cudaFuncAttributeMaxDynamicSharedMemorySize, FSMEM);

    const int XB = MROWS * DIM / 4 / 256;
    const int WB = DIM * DIM / 4 / 256;

    f32_to_bf16pair<<<XB, 256>>>(x, gxh, gxl);
    conv_w4<<<dim3(WB, 4), 256>>>(wq, wk, wv, wo, gwh, gwl);

    dim3 gg(DIM / 128, MROWS / 128);
    tc_gemm<<<gg, 256, TC_SMEM>>>(gxh, gxl, gwh + 0 * DD, gwl + 0 * DD, nullptr, qbh, qbl, fcos, fsin, DIM);
    tc_gemm<<<gg, 256, TC_SMEM>>>(gxh, gxl, gwh + 1 * DD, gwl + 1 * DD, nullptr, kbh, kbl, fcos, fsin, DIM);
    tc_gemm<<<gg, 256, TC_SMEM>>>(gxh, gxl, gwh + 2 * DD, gwl + 2 * DD, nullptr, vbh, vbl, nullptr, nullptr, DIM);
    lora_gemm<<<dim3(MROWS / 32, 2), 256>>>(x, waq, wak, qhh, qhl, khh, khl);

    flash_tc<<<dim3(SS / 128, BB * NH), 256, FSMEM>>>(qbh, qbl, kbh, kbl, vbh, vbl,
                                                      qhh, qhl, khh, khl, gaoh, gaol);

    tc_gemm<<<gg, 256, TC_SMEM>>>(gaoh, gaol, gwh + 3 * DD, gwl + 3 * DD, out, nullptr, nullptr, nullptr, nullptr, DIM);
}

// round 15
// speedup vs baseline: 1.1887x; 1.0672x over previous
#include <cuda_runtime.h>
#include <cuda_bf16.h>
#include <cstdint>

#define BB 2
#define SS 2048
#define DIM 2048
#define NH 16
#define HD 128
#define RANK 32
#define MROWS (BB*SS)
#define DD ((size_t)DIM*DIM)

// -------- scratch (device globals; no allocation allowed) --------
__device__ __nv_bfloat16 g_xh [MROWS*DIM];
__device__ __nv_bfloat16 g_xl [MROWS*DIM];
__device__ __nv_bfloat16 g_aoh[MROWS*DIM];
__device__ __nv_bfloat16 g_aol[MROWS*DIM];
__device__ __nv_bfloat16 g_wh [4][DIM*DIM];
__device__ __nv_bfloat16 g_wl [4][DIM*DIM];
__device__ __nv_bfloat16 g_qbh[MROWS*DIM];
__device__ __nv_bfloat16 g_qbl[MROWS*DIM];
__device__ __nv_bfloat16 g_kbh[MROWS*DIM];
__device__ __nv_bfloat16 g_kbl[MROWS*DIM];
__device__ __nv_bfloat16 g_vbh[MROWS*DIM];
__device__ __nv_bfloat16 g_vbl[MROWS*DIM];
__device__ __nv_bfloat16 g_qhh[MROWS*RANK];
__device__ __nv_bfloat16 g_qhl[MROWS*RANK];
__device__ __nv_bfloat16 g_khh[MROWS*RANK];
__device__ __nv_bfloat16 g_khl[MROWS*RANK];

__device__ __forceinline__ uint32_t smem_to_u32(const void* smem_ptr) {
    uint32_t addr;
    asm("{ .reg .u64 tmp; cvta.to.shared.u64 tmp, %1; cvt.u32.u64 %0, tmp; }"
        : "=r"(addr) : "l"(smem_ptr));
    return addr;
}
__device__ __forceinline__ void ldsm_x4(uint32_t& d0, uint32_t& d1, uint32_t& d2,
                                        uint32_t& d3, uint32_t addr) {
    asm volatile("ldmatrix.sync.aligned.m8n8.x4.shared.b16 {%0,%1,%2,%3}, [%4];"
                 : "=r"(d0), "=r"(d1), "=r"(d2), "=r"(d3) : "r"(addr));
}
__device__ __forceinline__ void ldsm_x4t(uint32_t& d0, uint32_t& d1, uint32_t& d2,
                                         uint32_t& d3, uint32_t addr) {
    asm volatile("ldmatrix.sync.aligned.m8n8.x4.trans.shared.b16 {%0,%1,%2,%3}, [%4];"
                 : "=r"(d0), "=r"(d1), "=r"(d2), "=r"(d3) : "r"(addr));
}
__device__ __forceinline__ void mma_bf16(float* c, const uint32_t* a,
                                         uint32_t b0, uint32_t b1) {
    asm volatile("mma.sync.aligned.m16n8k16.row.col.f32.bf16.bf16.f32 "
                 "{%0,%1,%2,%3}, {%4,%5,%6,%7}, {%8,%9}, {%0,%1,%2,%3};"
                 : "+f"(c[0]), "+f"(c[1]), "+f"(c[2]), "+f"(c[3])
                 : "r"(a[0]), "r"(a[1]), "r"(a[2]), "r"(a[3]), "r"(b0), "r"(b1));
}
__device__ __forceinline__ void cp16(uint32_t dst, const void* src) {
    asm volatile("cp.async.cg.shared.global [%0], [%1], 16;" :: "r"(dst), "l"(src));
}
#define CP_COMMIT()  asm volatile("cp.async.commit_group;" ::: "memory")
#define CP_WAIT(n)   asm volatile("cp.async.wait_group %0;" :: "n"(n) : "memory")

__device__ __forceinline__ float fast_rcp(float x) {
    float r; asm("rcp.approx.f32 %0, %1;" : "=f"(r) : "f"(x)); return r;
}
__device__ __forceinline__ float fast_ex2(float x) {
    float r; asm("ex2.approx.f32 %0, %1;" : "=f"(r) : "f"(x)); return r;
}

__device__ __forceinline__ void split2(float x, float y, uint32_t& hi, uint32_t& lo) {
    __nv_bfloat16 hx = __float2bfloat16(x), hy = __float2bfloat16(y);
    float rx = x - __bfloat162float(hx), ry = y - __bfloat162float(hy);
    __nv_bfloat162 H; H.x = hx; H.y = hy;
    __nv_bfloat162 L; L.x = __float2bfloat16(rx); L.y = __float2bfloat16(ry);
    hi = *(uint32_t*)&H; lo = *(uint32_t*)&L;
}

// ============================================================
// fp32 -> (bf16 hi, bf16 lo)
// ============================================================
__global__ __launch_bounds__(256) void f32_to_bf16pair(const float* __restrict__ in,
                                                       __nv_bfloat16* __restrict__ hi,
                                                       __nv_bfloat16* __restrict__ lo) {
    int i = blockIdx.x * 256 + threadIdx.x;
    float4 v = ((const float4*)in)[i];
    __nv_bfloat162 h0, h1, l0, l1;
    h0.x = __float2bfloat16(v.x); h0.y = __float2bfloat16(v.y);
    h1.x = __float2bfloat16(v.z); h1.y = __float2bfloat16(v.w);
    l0.x = __float2bfloat16(v.x - __bfloat162float(h0.x));
    l0.y = __float2bfloat16(v.y - __bfloat162float(h0.y));
    l1.x = __float2bfloat16(v.z - __bfloat162float(h1.x));
    l1.y = __float2bfloat16(v.w - __bfloat162float(h1.y));
    ((__nv_bfloat162*)hi)[2 * i]     = h0;
    ((__nv_bfloat162*)hi)[2 * i + 1] = h1;
    ((__nv_bfloat162*)lo)[2 * i]     = l0;
    ((__nv_bfloat162*)lo)[2 * i + 1] = l1;
}

// all 4 weights in one launch (gridDim.y = 4)
__global__ __launch_bounds__(256) void conv_w4(const float* __restrict__ w0,
                                               const float* __restrict__ w1,
                                               const float* __restrict__ w2,
                                               const float* __restrict__ w3,
                                               __nv_bfloat16* __restrict__ hi,
                                               __nv_bfloat16* __restrict__ lo) {
    int z = blockIdx.y;
    const float* in = (z == 0) ? w0 : (z == 1) ? w1 : (z == 2) ? w2 : w3;
    size_t off = (size_t)z * DD;
    int i = blockIdx.x * 256 + threadIdx.x;
    float4 v = ((const float4*)in)[i];
    __nv_bfloat162 h0, h1, l0, l1;
    h0.x = __float2bfloat16(v.x); h0.y = __float2bfloat16(v.y);
    h1.x = __float2bfloat16(v.z); h1.y = __float2bfloat16(v.w);
    l0.x = __float2bfloat16(v.x - __bfloat162float(h0.x));
    l0.y = __float2bfloat16(v.y - __bfloat162float(h0.y));
    l1.x = __float2bfloat16(v.z - __bfloat162float(h1.x));
    l1.y = __float2bfloat16(v.w - __bfloat162float(h1.y));
    ((__nv_bfloat162*)(hi + off))[2 * i]     = h0;
    ((__nv_bfloat162*)(hi + off))[2 * i + 1] = h1;
    ((__nv_bfloat162*)(lo + off))[2 * i]     = l0;
    ((__nv_bfloat162*)(lo + off))[2 * i + 1] = l1;
}

// ============================================================
// GEMM config (2-stage pipeline, pinned 2 CTAs/SM)
// ============================================================
#define KDIM 2048
#define TBK 32
#define NKIT (KDIM / TBK)
#define LDK 40
#define TILE_B (128 * LDK * 2)
#define STAGE_B (4 * TILE_B)
#define TC_SMEM (2 * STAGE_B)

// shared mainloop body as a macro to guarantee identical codegen
#define GEMM_MAINLOOP(Ahi_, Alo_, Bhi_, Blo_)                                          \
    const __nv_bfloat16* srcs[4] = { Ahi_, Alo_, Bhi_, Blo_ };                         \
    int l_tile[8], l_r[8], l_c[8];                                                     \
    _Pragma("unroll")                                                                  \
    for (int u = 0; u < 8; u++) {                                                      \
        int cid = u * 256 + tid;                                                       \
        l_tile[u] = cid >> 9;                                                          \
        int w = cid & 511;                                                             \
        l_r[u] = w >> 2;                                                               \
        l_c[u] = w & 3;                                                                \
    }                                                                                  \
    auto issue_stage = [&](int it, int stage) {                                        \
        uint32_t base = sb + stage * STAGE_B;                                          \
        int k0 = it * TBK;                                                             \
        _Pragma("unroll")                                                              \
        for (int u = 0; u < 8; u++) {                                                  \
            uint32_t dst = base + l_tile[u] * TILE_B + l_r[u] * (LDK * 2) + l_c[u] * 16;\
            const __nv_bfloat16* src = srcs[l_tile[u]] + (size_t)l_r[u] * KDIM + k0 + l_c[u] * 8;\
            cp16(dst, src);                                                            \
        }                                                                              \
        CP_COMMIT();                                                                   \
    };                                                                                 \
    float acc[2][8][4];                                                                \
    _Pragma("unroll")                                                                  \
    for (int i = 0; i < 2; i++)                                                        \
        _Pragma("unroll")                                                              \
        for (int j = 0; j < 8; j++)                                                    \
            _Pragma("unroll")                                                          \
            for (int q = 0; q < 4; q++) acc[i][j][q] = 0.f;                            \
    const int lrow = lane & 15;                                                        \
    const int lcol = (lane >> 4) * 8;                                                  \
    issue_stage(0, 0);                                                                 \
    for (int it = 0; it < NKIT; it++) {                                                \
        int cur = it & 1;                                                              \
        if (it + 1 < NKIT) { issue_stage(it + 1, cur ^ 1); CP_WAIT(1); }               \
        else { CP_WAIT(0); }                                                           \
        __syncthreads();                                                               \
        uint32_t base = sb + cur * STAGE_B;                                            \
        uint32_t aA_hi = base + 0 * TILE_B;                                            \
        uint32_t aA_lo = base + 1 * TILE_B;                                            \
        uint32_t aB_hi = base + 2 * TILE_B;                                            \
        uint32_t aB_lo = base + 3 * TILE_B;                                            \
        _Pragma("unroll")                                                              \
        for (int ks = 0; ks < 2; ks++) {                                               \
            const int kc = ks * 16 + lcol;                                             \
            uint32_t ah[2][4], al[2][4], bh[4][4], bl[4][4];                           \
            _Pragma("unroll")                                                          \
            for (int ma = 0; ma < 2; ma++) {                                           \
                uint32_t off = (wm + ma * 16 + lrow) * (LDK * 2) + kc * 2;             \
                ldsm_x4(ah[ma][0], ah[ma][1], ah[ma][2], ah[ma][3], aA_hi + off);      \
                ldsm_x4(al[ma][0], al[ma][1], al[ma][2], al[ma][3], aA_lo + off);      \
            }                                                                          \
            _Pragma("unroll")                                                          \
            for (int nb = 0; nb < 4; nb++) {                                           \
                uint32_t off = (wn + nb * 16 + lrow) * (LDK * 2) + kc * 2;             \
                ldsm_x4(bh[nb][0], bh[nb][1], bh[nb][2], bh[nb][3], aB_hi + off);      \
                ldsm_x4(bl[nb][0], bl[nb][1], bl[nb][2], bl[nb][3], aB_lo + off);      \
            }                                                                          \
            _Pragma("unroll")                                                          \
            for (int ma = 0; ma < 2; ma++)                                             \
                _Pragma("unroll")                                                      \
                for (int nb = 0; nb < 4; nb++) {                                       \
                    mma_bf16(acc[ma][nb * 2],     ah[ma], bh[nb][0], bh[nb][2]);       \
                    mma_bf16(acc[ma][nb * 2 + 1], ah[ma], bh[nb][1], bh[nb][3]);       \
                    mma_bf16(acc[ma][nb * 2],     ah[ma], bl[nb][0], bl[nb][2]);       \
                    mma_bf16(acc[ma][nb * 2 + 1], ah[ma], bl[nb][1], bl[nb][3]);       \
                    mma_bf16(acc[ma][nb * 2],     al[ma], bh[nb][0], bh[nb][2]);       \
                    mma_bf16(acc[ma][nb * 2 + 1], al[ma], bh[nb][1], bh[nb][3]);       \
                }                                                                      \
        }                                                                              \
        __syncthreads();                                                               \
    }

// ============================================================
// QKV GEMM, all three in one launch (blockIdx.z selects weight),
// bf16 pair out + fused RoPE for q,k. Pinned 2 CTAs/SM.
// ============================================================
__global__ __launch_bounds__(256, 2) void qkv_gemm(const __nv_bfloat16* __restrict__ Xhi,
                                                   const __nv_bfloat16* __restrict__ Xlo,
                                                   const __nv_bfloat16* __restrict__ Wh,
                                                   const __nv_bfloat16* __restrict__ Wl,
                                                   __nv_bfloat16* __restrict__ Qh, __nv_bfloat16* __restrict__ Ql,
                                                   __nv_bfloat16* __restrict__ Kh, __nv_bfloat16* __restrict__ Kl,
                                                   __nv_bfloat16* __restrict__ Vh, __nv_bfloat16* __restrict__ Vl,
                                                   const float* __restrict__ cs,
                                                   const float* __restrict__ sn) {
    extern __shared__ char smem[];
    const uint32_t sb = smem_to_u32(smem);
    const int tid = threadIdx.x;
    const int wid = tid >> 5, lane = tid & 31;
    const int m0 = blockIdx.y * 128;
    const int n0 = blockIdx.x * 128;
    const int z = blockIdx.z;
    const int wm = (wid & 3) * 32;
    const int wn = (wid >> 2) * 64;

    GEMM_MAINLOOP(Xhi + (size_t)m0 * KDIM, Xlo + (size_t)m0 * KDIM,
                  Wh + (size_t)z * DD + (size_t)n0 * KDIM,
                  Wl + (size_t)z * DD + (size_t)n0 * KDIM)

    __nv_bfloat16* Chi = (z == 0) ? Qh : (z == 1) ? Kh : Vh;
    __nv_bfloat16* Clo = (z == 0) ? Ql : (z == 1) ? Kl : Vl;
    const bool dorope = (z < 2);

    const int er = lane >> 2;
    const int ec = (lane & 3) * 2;
#pragma unroll
    for (int ma = 0; ma < 2; ma++)
#pragma unroll
        for (int na = 0; na < 8; na++) {
            int row = m0 + wm + ma * 16 + er;
            int col = n0 + wn + na * 8 + ec;
            float a0 = acc[ma][na][0], a1 = acc[ma][na][1];
            float a2 = acc[ma][na][2], a3 = acc[ma][na][3];
            if (dorope) {
                int p = (col & 127) >> 1;
                int s0 = row & (SS - 1), s1 = (row + 8) & (SS - 1);
                float c0 = cs[s0 * 64 + p], v0 = sn[s0 * 64 + p];
                float c1 = cs[s1 * 64 + p], v1 = sn[s1 * 64 + p];
                float t;
                t = a0 * c0 - a1 * v0; a1 = a0 * v0 + a1 * c0; a0 = t;
                t = a2 * c1 - a3 * v1; a3 = a2 * v1 + a3 * c1; a2 = t;
            }
            size_t i0 = (size_t)row * DIM + col;
            size_t i1 = (size_t)(row + 8) * DIM + col;
            uint32_t h, l;
            split2(a0, a1, h, l);
            *(uint32_t*)(Chi + i0) = h; *(uint32_t*)(Clo + i0) = l;
            split2(a2, a3, h, l);
            *(uint32_t*)(Chi + i1) = h; *(uint32_t*)(Clo + i1) = l;
        }
}

// ============================================================
// output projection (fp32 out), pinned 2 CTAs/SM
// ============================================================
__global__ __launch_bounds__(256, 2) void tc_gemm_f32(const __nv_bfloat16* __restrict__ Ahi,
                                                      const __nv_bfloat16* __restrict__ Alo,
                                                      const __nv_bfloat16* __restrict__ Bhi,
                                                      const __nv_bfloat16* __restrict__ Blo,
                                                      float* __restrict__ C) {
    extern __shared__ char smem[];
    const uint32_t sb = smem_to_u32(smem);
    const int tid = threadIdx.x;
    const int wid = tid >> 5, lane = tid & 31;
    const int m0 = blockIdx.y * 128;
    const int n0 = blockIdx.x * 128;
    const int wm = (wid & 3) * 32;
    const int wn = (wid >> 2) * 64;

    GEMM_MAINLOOP(Ahi + (size_t)m0 * KDIM, Alo + (size_t)m0 * KDIM,
                  Bhi + (size_t)n0 * KDIM, Blo + (size_t)n0 * KDIM)

    const int er = lane >> 2;
    const int ec = (lane & 3) * 2;
#pragma unroll
    for (int ma = 0; ma < 2; ma++)
#pragma unroll
        for (int na = 0; na < 8; na++) {
            int row = m0 + wm + ma * 16 + er;
            int col = n0 + wn + na * 8 + ec;
            float* p0 = C + (size_t)row * DIM + col;
            float* p1 = C + (size_t)(row + 8) * DIM + col;
            p0[0] = acc[ma][na][0]; p0[1] = acc[ma][na][1];
            p1[0] = acc[ma][na][2]; p1[1] = acc[ma][na][3];
        }
}

// ============================================================
// LoRA projection: 32-row blocks, both heads in one launch (y=2),
// float4 global loads
// ============================================================
__global__ __launch_bounds__(256) void lora_gemm(const float* __restrict__ X,
                                                 const float* __restrict__ Wq,
                                                 const float* __restrict__ Wk,
                                                 __nv_bfloat16* __restrict__ Qh,
                                                 __nv_bfloat16* __restrict__ Ql,
                                                 __nv_bfloat16* __restrict__ Kh,
                                                 __nv_bfloat16* __restrict__ Kl) {
    __shared__ float xs[32][33];
    __shared__ float ws[32][33];
    const float* W = blockIdx.y ? Wk : Wq;
    __nv_bfloat16* Ch = blockIdx.y ? Kh : Qh;
    __nv_bfloat16* Cl = blockIdx.y ? Kl : Ql;
    const int tid = threadIdx.x;
    const int lane = tid & 31, wrp = tid >> 5;
    const int m0 = blockIdx.x * 32;
    const int vr = tid >> 3, vc = (tid & 7) * 4;
    float acc[4] = {0.f, 0.f, 0.f, 0.f};

    for (int k0 = 0; k0 < DIM; k0 += 32) {
        __syncthreads();
        {
            float4 xv = *(const float4*)&X[(size_t)(m0 + vr) * DIM + k0 + vc];
            xs[vr][vc] = xv.x; xs[vr][vc + 1] = xv.y;
            xs[vr][vc + 2] = xv.z; xs[vr][vc + 3] = xv.w;
            float4 wv4 = *(const float4*)&W[(size_t)vr * DIM + k0 + vc];
            ws[vr][vc] = wv4.x; ws[vr][vc + 1] = wv4.y;
            ws[vr][vc + 2] = wv4.z; ws[vr][vc + 3] = wv4.w;
        }
        __syncthreads();
#pragma unroll
        for (int kk = 0; kk < 32; kk++) {
            float wv = ws[lane][kk];
#pragma unroll
            for (int i = 0; i < 4; i++)
                acc[i] = fmaf(xs[wrp * 4 + i][kk], wv, acc[i]);
        }
    }
#pragma unroll
    for (int i = 0; i < 4; i++) {
        size_t idx = (size_t)(m0 + wrp * 4 + i) * RANK + lane;
        __nv_bfloat16 hv = __float2bfloat16(acc[i]);
        Ch[idx] = hv;
        Cl[idx] = __float2bfloat16(acc[i] - __bfloat162float(hv));
    }
}

// ============================================================
// Tensor-core flash attention (R12/R14 winner, unchanged)
// ============================================================
#define SQB 272
#define SRB 80
#define KTILE 17408
#define KSTG  (2 * KTILE)
#define HTILE 5120
#define HSTG  (2 * HTILE)
#define oQh 0
#define oQl 34816
#define oK  69632
#define oV  139264
#define oqh 174080
#define oql 184320
#define okh 194560
#define FSMEM 215040

__global__ __launch_bounds__(256) void flash_tc(
    const __nv_bfloat16* __restrict__ Qh_, const __nv_bfloat16* __restrict__ Ql_,
    const __nv_bfloat16* __restrict__ Kh_, const __nv_bfloat16* __restrict__ Kl_,
    const __nv_bfloat16* __restrict__ Vh_, const __nv_bfloat16* __restrict__ Vl_,
    const __nv_bfloat16* __restrict__ QHh_, const __nv_bfloat16* __restrict__ QHl_,
    const __nv_bfloat16* __restrict__ KHh_, const __nv_bfloat16* __restrict__ KHl_,
    __nv_bfloat16* __restrict__ Oh, __nv_bfloat16* __restrict__ Ol) {
    extern __shared__ char sm[];
    const uint32_t sb = smem_to_u32(sm);
    const int tid = threadIdx.x, lane = tid & 31, wid = tid >> 5;
    const int qt = gridDim.x - 1 - blockIdx.x;
    const int b = blockIdx.y >> 4, h = blockIdx.y & 15;
    const int q0 = qt * 128;
    const size_t rowbase = (size_t)b * SS;
    const int wm = wid * 16;
    const int lrow = lane & 15, lcol = (lane >> 4) * 8;
    const float SC2 = 0.08838834764831845f * 1.4426950408889634f;
    const float L2E = 1.4426950408889634f;

    auto issue_K = [&](int kt) {
        int nk0 = min(kt * 64, SS - 64);
        int stg = kt & 1;
        uint32_t bKh = sb + oK + stg * KSTG;
        uint32_t bKl = bKh + KTILE;
#pragma unroll
        for (int u = 0; u < 4; u++) {
            int cid = u * 256 + tid;
            int row = cid >> 4, col = cid & 15;
            size_t g = (rowbase + nk0 + row) * DIM + h * HD + col * 8;
            cp16(bKh + row * SQB + col * 16, Kh_ + g);
            cp16(bKl + row * SQB + col * 16, Kl_ + g);
        }
        uint32_t bkh = sb + okh + stg * HSTG;
        {
            int row = tid >> 2, col = tid & 3;
            size_t g = (rowbase + nk0 + row) * RANK + col * 8;
            cp16(bkh + row * SRB + col * 16, KHh_ + g);
            cp16(bkh + HTILE + row * SRB + col * 16, KHl_ + g);
        }
        CP_COMMIT();
    };
    auto issue_V = [&](int kt) {
        int nk0 = min(kt * 64, SS - 64);
#pragma unroll
        for (int u = 0; u < 4; u++) {
            int cid = u * 256 + tid;
            int row = cid >> 4, col = cid & 15;
            size_t g = (rowbase + nk0 + row) * DIM + h * HD + col * 8;
            cp16(sb + oV + row * SQB + col * 16, Vh_ + g);
            cp16(sb + oV + KTILE + row * SQB + col * 16, Vl_ + g);
        }
        CP_COMMIT();
    };

    {
#pragma unroll
        for (int u = 0; u < 8; u++) {
            int cid = u * 256 + tid;
            int row = cid >> 4, col = cid & 15;
            size_t g = (rowbase + q0 + row) * DIM + h * HD + col * 8;
            cp16(sb + oQh + row * SQB + col * 16, Qh_ + g);
            cp16(sb + oQl + row * SQB + col * 16, Ql_ + g);
        }
#pragma unroll
        for (int u = 0; u < 2; u++) {
            int cid = u * 256 + tid;
            int row = cid >> 2, col = cid & 3;
            size_t g = (rowbase + q0 + row) * RANK + col * 8;
            cp16(sb + oqh + row * SRB + col * 16, QHh_ + g);
            cp16(sb + oql + row * SRB + col * 16, QHl_ + g);
        }
        CP_COMMIT();
    }
    issue_K(0);
    issue_V(0);

    uint32_t qf[8][2][4];
    uint32_t qhf[2][2][4];
    CP_WAIT(2);
    __syncthreads();
#pragma unroll
    for (int ks = 0; ks < 8; ks++) {
        const int kc = ks * 16 + lcol;
        uint32_t off = (wm + lrow) * SQB + kc * 2;
        ldsm_x4(qf[ks][0][0], qf[ks][0][1], qf[ks][0][2], qf[ks][0][3], sb + oQh + off);
        ldsm_x4(qf[ks][1][0], qf[ks][1][1], qf[ks][1][2], qf[ks][1][3], sb + oQl + off);
    }
#pragma unroll
    for (int ks = 0; ks < 2; ks++) {
        const int kc = ks * 16 + lcol;
        uint32_t off = (wm + lrow) * SRB + kc * 2;
        ldsm_x4(qhf[ks][0][0], qhf[ks][0][1], qhf[ks][0][2], qhf[ks][0][3], sb + oqh + off);
        ldsm_x4(qhf[ks][1][0], qhf[ks][1][1], qhf[ks][1][2], qhf[ks][1][3], sb + oql + off);
    }

    float o[16][4];
#pragma unroll
    for (int i = 0; i < 16; i++)
#pragma unroll
        for (int e = 0; e < 4; e++) o[i][e] = 0.f;
    float m0 = -1e30f, m1 = -1e30f, l0 = 0.f, l1 = 0.f;

    const int nkt = q0 / 64 + 2;
    for (int kt = 0; kt < nkt; kt++) {
        const int k0 = kt * 64;
        const int kb = kt & 1;
        CP_WAIT(1);
        __syncthreads();
        issue_K(kt + 1);

        const bool skip = (k0 > q0 + wm + 15);
        float s[8][4];
        if (!skip) {
            const uint32_t bKh = sb + oK + kb * KSTG, bKl = bKh + KTILE;
            const uint32_t bkh = sb + okh + kb * HSTG, bkl = bkh + HTILE;

            float gg[8][4];
#pragma unroll
            for (int i = 0; i < 8; i++)
#pragma unroll
                for (int e = 0; e < 4; e++) gg[i][e] = 0.f;
#pragma unroll
            for (int ks = 0; ks < 2; ks++) {
#pragma unroll
                for (int nb = 0; nb < 4; nb++) {
                    uint32_t bh[4], bl[4];
                    uint32_t boff = (nb * 16 + lrow) * SRB + (ks * 16 + lcol) * 2;
                    ldsm_x4(bh[0], bh[1], bh[2], bh[3], bkh + boff);
                    ldsm_x4(bl[0], bl[1], bl[2], bl[3], bkl + boff);
                    mma_bf16(gg[nb * 2],     qhf[ks][0], bh[0], bh[2]);
                    mma_bf16(gg[nb * 2],     qhf[ks][0], bl[0], bl[2]);
                    mma_bf16(gg[nb * 2],     qhf[ks][1], bh[0], bh[2]);
                    mma_bf16(gg[nb * 2 + 1], qhf[ks][0], bh[1], bh[3]);
                    mma_bf16(gg[nb * 2 + 1], qhf[ks][0], bl[1], bl[3]);
                    mma_bf16(gg[nb * 2 + 1], qhf[ks][1], bh[1], bh[3]);
                }
            }
#pragma unroll
            for (int i = 0; i < 8; i++)
#pragma unroll
                for (int e = 0; e < 4; e++)
                    gg[i][e] = fast_rcp(1.f + fast_ex2(-L2E * gg[i][e]));

#pragma unroll
            for (int i = 0; i < 8; i++)
#pragma unroll
                for (int e = 0; e < 4; e++) s[i][e] = 0.f;
#pragma unroll
            for (int ks = 0; ks < 8; ks++) {
#pragma unroll
                for (int nb = 0; nb < 4; nb++) {
                    uint32_t bh[4], bl[4];
                    uint32_t boff = (nb * 16 + lrow) * SQB + (ks * 16 + lcol) * 2;
                    ldsm_x4(bh[0], bh[1], bh[2], bh[3], bKh + boff);
                    ldsm_x4(bl[0], bl[1], bl[2], bl[3], bKl + boff);
                    mma_bf16(s[nb * 2],     qf[ks][0], bh[0], bh[2]);
                    mma_bf16(s[nb * 2],     qf[ks][0], bl[0], bl[2]);
                    mma_bf16(s[nb * 2],     qf[ks][1], bh[0], bh[2]);
                    mma_bf16(s[nb * 2 + 1], qf[ks][0], bh[1], bh[3]);
                    mma_bf16(s[nb * 2 + 1], qf[ks][0], bl[1], bl[3]);
                    mma_bf16(s[nb * 2 + 1], qf[ks][1], bh[1], bh[3]);
                }
            }

            const int r0g = q0 + wm + (lane >> 2);
            if (k0 + 64 > q0 + wm) {
#pragma unroll
                for (int na = 0; na < 8; na++)
#pragma unroll
                    for (int e = 0; e < 4; e++) {
                        int key = k0 + na * 8 + (lane & 3) * 2 + (e & 1);
                        int row = r0g + (e >> 1) * 8;
                        s[na][e] = (key <= row) ? s[na][e] * SC2 : -1e30f;
                    }
            } else {
#pragma unroll
                for (int na = 0; na < 8; na++)
#pragma unroll
                    for (int e = 0; e < 4; e++) s[na][e] *= SC2;
            }

            float mx0 = -1e30f, mx1 = -1e30f;
#pragma unroll
            for (int na = 0; na < 8; na++) {
                mx0 = fmaxf(mx0, fmaxf(s[na][0], s[na][1]));
                mx1 = fmaxf(mx1, fmaxf(s[na][2], s[na][3]));
            }
            mx0 = fmaxf(mx0, __shfl_xor_sync(0xffffffffu, mx0, 1));
            mx0 = fmaxf(mx0, __shfl_xor_sync(0xffffffffu, mx0, 2));
            mx1 = fmaxf(mx1, __shfl_xor_sync(0xffffffffu, mx1, 1));
            mx1 = fmaxf(mx1, __shfl_xor_sync(0xffffffffu, mx1, 2));
            float mn0 = fmaxf(m0, mx0), mn1 = fmaxf(m1, mx1);
            float al0 = fast_ex2(m0 - mn0), al1 = fast_ex2(m1 - mn1);
            m0 = mn0; m1 = mn1;
            float rs0 = 0.f, rs1 = 0.f;
#pragma unroll
            for (int na = 0; na < 8; na++) {
                s[na][0] = fast_ex2(s[na][0] - m0); rs0 += s[na][0];
                s[na][1] = fast_ex2(s[na][1] - m0); rs0 += s[na][1];
                s[na][2] = fast_ex2(s[na][2] - m1); rs1 += s[na][2];
                s[na][3] = fast_ex2(s[na][3] - m1); rs1 += s[na][3];
            }
            rs0 += __shfl_xor_sync(0xffffffffu, rs0, 1);
            rs0 += __shfl_xor_sync(0xffffffffu, rs0, 2);
            rs1 += __shfl_xor_sync(0xffffffffu, rs1, 1);
            rs1 += __shfl_xor_sync(0xffffffffu, rs1, 2);
            l0 = l0 * al0 + rs0;
            l1 = l1 * al1 + rs1;
            if (al0 != 1.f || al1 != 1.f) {
#pragma unroll
                for (int na = 0; na < 16; na++) {
                    o[na][0] *= al0; o[na][1] *= al0;
                    o[na][2] *= al1; o[na][3] *= al1;
                }
            }
#pragma unroll
            for (int na = 0; na < 8; na++)
#pragma unroll
                for (int e = 0; e < 4; e++) s[na][e] *= gg[na][e];
        }

        CP_WAIT(1);
        __syncthreads();

        if (!skip) {
#pragma unroll
            for (int j = 0; j < 4; j++) {
                uint32_t wa[4], wl[4];
                split2(s[2 * j][0],     s[2 * j][1],     wa[0], wl[0]);
                split2(s[2 * j][2],     s[2 * j][3],     wa[1], wl[1]);
                split2(s[2 * j + 1][0], s[2 * j + 1][1], wa[2], wl[2]);
                split2(s[2 * j + 1][2], s[2 * j + 1][3], wa[3], wl[3]);
#pragma unroll
                for (int dp = 0; dp < 8; dp++) {
                    uint32_t vh[4], vl[4];
                    uint32_t voff = (j * 16 + lrow) * SQB + (dp * 16 + lcol) * 2;
                    ldsm_x4t(vh[0], vh[1], vh[2], vh[3], sb + oV + voff);
                    ldsm_x4t(vl[0], vl[1], vl[2], vl[3], sb + oV + KTILE + voff);
                    mma_bf16(o[dp * 2],     wa, vh[0], vh[1]);
                    mma_bf16(o[dp * 2],     wa, vl[0], vl[1]);
                    mma_bf16(o[dp * 2],     wl, vh[0], vh[1]);
                    mma_bf16(o[dp * 2 + 1], wa, vh[2], vh[3]);
                    mma_bf16(o[dp * 2 + 1], wa, vl[2], vl[3]);
                    mma_bf16(o[dp * 2 + 1], wl, vh[2], vh[3]);
                }
            }
        }
        __syncthreads();
        issue_V(kt + 1);
    }

    const float inv0 = fast_rcp(l0), inv1 = fast_rcp(l1);
    const int row0 = q0 + wm + (lane >> 2);
    size_t base0 = (rowbase + row0) * DIM + h * HD;
    size_t base1 = base0 + 8 * (size_t)DIM;
#pragma unroll
    for (int na = 0; na < 16; na++) {
        int d = na * 8 + (lane & 3) * 2;
        uint32_t hv, lv;
        split2(o[na][0] * inv0, o[na][1] * inv0, hv, lv);
        *(uint32_t*)(Oh + base0 + d) = hv;
        *(uint32_t*)(Ol + base0 + d) = lv;
        split2(o[na][2] * inv1, o[na][3] * inv1, hv, lv);
        *(uint32_t*)(Oh + base1 + d) = hv;
        *(uint32_t*)(Ol + base1 + d) = lv;
    }
}

// ============================================================
// launch
// ============================================================
extern "C" void kernel_launch(void* const* d_in, const int* in_sizes, int n_in,
                              void* d_out, int out_size) {
    const float* x    = (const float*)d_in[0];
    const float* fcos = (const float*)d_in[2];
    const float* fsin = (const float*)d_in[3];
    const float* wq   = (const float*)d_in[4];
    const float* wk   = (const float*)d_in[5];
    const float* wv   = (const float*)d_in[6];
    const float* wo   = (const float*)d_in[7];
    const float* waq  = (const float*)d_in[8];
    const float* wak  = (const float*)d_in[9];
    float* out = (float*)d_out;

    __nv_bfloat16 *gxh, *gxl, *gaoh, *gaol, *gwh, *gwl;
    __nv_bfloat16 *qbh, *qbl, *kbh, *kbl, *vbh, *vbl, *qhh, *qhl, *khh, *khl;
    cudaGetSymbolAddress((void**)&gxh, g_xh);
    cudaGetSymbolAddress((void**)&gxl, g_xl);
    cudaGetSymbolAddress((void**)&gaoh, g_aoh);
    cudaGetSymbolAddress((void**)&gaol, g_aol);
    cudaGetSymbolAddress((void**)&gwh, g_wh);
    cudaGetSymbolAddress((void**)&gwl, g_wl);
    cudaGetSymbolAddress((void**)&qbh, g_qbh);
    cudaGetSymbolAddress((void**)&qbl, g_qbl);
    cudaGetSymbolAddress((void**)&kbh, g_kbh);
    cudaGetSymbolAddress((void**)&kbl, g_kbl);
    cudaGetSymbolAddress((void**)&vbh, g_vbh);
    cudaGetSymbolAddress((void**)&vbl, g_vbl);
    cudaGetSymbolAddress((void**)&qhh, g_qhh);
    cudaGetSymbolAddress((void**)&qhl, g_qhl);
    cudaGetSymbolAddress((void**)&khh, g_khh);
    cudaGetSymbolAddress((void**)&khl, g_khl);

    cudaFuncSetAttribute(qkv_gemm, cudaFuncAttributeMaxDynamicSharedMemorySize, TC_SMEM);
    cudaFuncSetAttribute(tc_gemm_f32, cudaFuncAttributeMaxDynamicSharedMemorySize, TC_SMEM);
    cudaFuncSetAttribute(flash_tc, cudaFuncAttributeMaxDynamicSharedMemorySize, FSMEM);

    const int XB = MROWS * DIM / 4 / 256;
    const int WB = DIM * DIM / 4 / 256;

    f32_to_bf16pair<<<XB, 256>>>(x, gxh, gxl);
    conv_w4<<<dim3(WB, 4), 256>>>(wq, wk, wv, wo, gwh, gwl);

    qkv_gemm<<<dim3(DIM / 128, MROWS / 128, 3), 256, TC_SMEM>>>(
        gxh, gxl, gwh, gwl, qbh, qbl, kbh, kbl, vbh, vbl, fcos, fsin);
    lora_gemm<<<dim3(MROWS / 32, 2), 256>>>(x, waq, wak, qhh, qhl, khh, khl);

    flash_tc<<<dim3(SS / 128, BB * NH), 256, FSMEM>>>(qbh, qbl, kbh, kbl, vbh, vbl,
                                                      qhh, qhl, khh, khl, gaoh, gaol);

    tc_gemm_f32<<<dim3(DIM / 128, MROWS / 128), 256, TC_SMEM>>>(
        gaoh, gaol, gwh + 3 * DD, gwl + 3 * DD, out);
}

// round 16
// speedup vs baseline: 1.2195x; 1.0259x over previous
#include <cuda_runtime.h>
#include <cuda_bf16.h>
#include <cstdint>

#define BB 2
#define SS 2048
#define DIM 2048
#define NH 16
#define HD 128
#define RANK 32
#define MROWS (BB*SS)
#define DD ((size_t)DIM*DIM)

// -------- scratch (device globals; no allocation allowed) --------
__device__ __nv_bfloat16 g_xh [MROWS*DIM];
__device__ __nv_bfloat16 g_xl [MROWS*DIM];
__device__ __nv_bfloat16 g_aoh[MROWS*DIM];
__device__ __nv_bfloat16 g_aol[MROWS*DIM];
__device__ __nv_bfloat16 g_wh [4][DIM*DIM];
__device__ __nv_bfloat16 g_wl [4][DIM*DIM];
__device__ __nv_bfloat16 g_qbh[MROWS*DIM];
__device__ __nv_bfloat16 g_qbl[MROWS*DIM];
__device__ __nv_bfloat16 g_kbh[MROWS*DIM];
__device__ __nv_bfloat16 g_kbl[MROWS*DIM];
__device__ __nv_bfloat16 g_vbh[MROWS*DIM];
__device__ __nv_bfloat16 g_vbl[MROWS*DIM];
__device__ __nv_bfloat16 g_qhh[MROWS*RANK];
__device__ __nv_bfloat16 g_qhl[MROWS*RANK];
__device__ __nv_bfloat16 g_khh[MROWS*RANK];
__device__ __nv_bfloat16 g_khl[MROWS*RANK];
__device__ __nv_bfloat16 g_lwh[2][RANK*DIM];
__device__ __nv_bfloat16 g_lwl[2][RANK*DIM];

__device__ __forceinline__ uint32_t smem_to_u32(const void* smem_ptr) {
    uint32_t addr;
    asm("{ .reg .u64 tmp; cvta.to.shared.u64 tmp, %1; cvt.u32.u64 %0, tmp; }"
        : "=r"(addr) : "l"(smem_ptr));
    return addr;
}
__device__ __forceinline__ void ldsm_x4(uint32_t& d0, uint32_t& d1, uint32_t& d2,
                                        uint32_t& d3, uint32_t addr) {
    asm volatile("ldmatrix.sync.aligned.m8n8.x4.shared.b16 {%0,%1,%2,%3}, [%4];"
                 : "=r"(d0), "=r"(d1), "=r"(d2), "=r"(d3) : "r"(addr));
}
__device__ __forceinline__ void ldsm_x4t(uint32_t& d0, uint32_t& d1, uint32_t& d2,
                                         uint32_t& d3, uint32_t addr) {
    asm volatile("ldmatrix.sync.aligned.m8n8.x4.trans.shared.b16 {%0,%1,%2,%3}, [%4];"
                 : "=r"(d0), "=r"(d1), "=r"(d2), "=r"(d3) : "r"(addr));
}
__device__ __forceinline__ void mma_bf16(float* c, const uint32_t* a,
                                         uint32_t b0, uint32_t b1) {
    asm volatile("mma.sync.aligned.m16n8k16.row.col.f32.bf16.bf16.f32 "
                 "{%0,%1,%2,%3}, {%4,%5,%6,%7}, {%8,%9}, {%0,%1,%2,%3};"
                 : "+f"(c[0]), "+f"(c[1]), "+f"(c[2]), "+f"(c[3])
                 : "r"(a[0]), "r"(a[1]), "r"(a[2]), "r"(a[3]), "r"(b0), "r"(b1));
}
__device__ __forceinline__ void cp16(uint32_t dst, const void* src) {
    asm volatile("cp.async.cg.shared.global [%0], [%1], 16;" :: "r"(dst), "l"(src));
}
#define CP_COMMIT()  asm volatile("cp.async.commit_group;" ::: "memory")
#define CP_WAIT(n)   asm volatile("cp.async.wait_group %0;" :: "n"(n) : "memory")

__device__ __forceinline__ float fast_rcp(float x) {
    float r; asm("rcp.approx.f32 %0, %1;" : "=f"(r) : "f"(x)); return r;
}
__device__ __forceinline__ float fast_ex2(float x) {
    float r; asm("ex2.approx.f32 %0, %1;" : "=f"(r) : "f"(x)); return r;
}

__device__ __forceinline__ void split2(float x, float y, uint32_t& hi, uint32_t& lo) {
    __nv_bfloat16 hx = __float2bfloat16(x), hy = __float2bfloat16(y);
    float rx = x - __bfloat162float(hx), ry = y - __bfloat162float(hy);
    __nv_bfloat162 H; H.x = hx; H.y = hy;
    __nv_bfloat162 L; L.x = __float2bfloat16(rx); L.y = __float2bfloat16(ry);
    hi = *(uint32_t*)&H; lo = *(uint32_t*)&L;
}

// ============================================================
// fp32 -> (bf16 hi, bf16 lo)
// ============================================================
__global__ __launch_bounds__(256) void f32_to_bf16pair(const float* __restrict__ in,
                                                       __nv_bfloat16* __restrict__ hi,
                                                       __nv_bfloat16* __restrict__ lo) {
    int i = blockIdx.x * 256 + threadIdx.x;
    float4 v = ((const float4*)in)[i];
    __nv_bfloat162 h0, h1, l0, l1;
    h0.x = __float2bfloat16(v.x); h0.y = __float2bfloat16(v.y);
    h1.x = __float2bfloat16(v.z); h1.y = __float2bfloat16(v.w);
    l0.x = __float2bfloat16(v.x - __bfloat162float(h0.x));
    l0.y = __float2bfloat16(v.y - __bfloat162float(h0.y));
    l1.x = __float2bfloat16(v.z - __bfloat162float(h1.x));
    l1.y = __float2bfloat16(v.w - __bfloat162float(h1.y));
    ((__nv_bfloat162*)hi)[2 * i]     = h0;
    ((__nv_bfloat162*)hi)[2 * i + 1] = h1;
    ((__nv_bfloat162*)lo)[2 * i]     = l0;
    ((__nv_bfloat162*)lo)[2 * i + 1] = l1;
}

// all 4 weights in one launch (gridDim.y = 4)
__global__ __launch_bounds__(256) void conv_w4(const float* __restrict__ w0,
                                               const float* __restrict__ w1,
                                               const float* __restrict__ w2,
                                               const float* __restrict__ w3,
                                               __nv_bfloat16* __restrict__ hi,
                                               __nv_bfloat16* __restrict__ lo) {
    int z = blockIdx.y;
    const float* in = (z == 0) ? w0 : (z == 1) ? w1 : (z == 2) ? w2 : w3;
    size_t off = (size_t)z * DD;
    int i = blockIdx.x * 256 + threadIdx.x;
    float4 v = ((const float4*)in)[i];
    __nv_bfloat162 h0, h1, l0, l1;
    h0.x = __float2bfloat16(v.x); h0.y = __float2bfloat16(v.y);
    h1.x = __float2bfloat16(v.z); h1.y = __float2bfloat16(v.w);
    l0.x = __float2bfloat16(v.x - __bfloat162float(h0.x));
    l0.y = __float2bfloat16(v.y - __bfloat162float(h0.y));
    l1.x = __float2bfloat16(v.z - __bfloat162float(h1.x));
    l1.y = __float2bfloat16(v.w - __bfloat162float(h1.y));
    ((__nv_bfloat162*)(hi + off))[2 * i]     = h0;
    ((__nv_bfloat162*)(hi + off))[2 * i + 1] = h1;
    ((__nv_bfloat162*)(lo + off))[2 * i]     = l0;
    ((__nv_bfloat162*)(lo + off))[2 * i + 1] = l1;
}

// lora weights (32x2048 each, gridDim.y = 2)
__global__ __launch_bounds__(256) void conv_lw(const float* __restrict__ wq,
                                               const float* __restrict__ wk,
                                               __nv_bfloat16* __restrict__ hi,
                                               __nv_bfloat16* __restrict__ lo) {
    int z = blockIdx.y;
    const float* in = z ? wk : wq;
    size_t off = (size_t)z * (RANK * DIM);
    int i = blockIdx.x * 256 + threadIdx.x;
    float4 v = ((const float4*)in)[i];
    __nv_bfloat162 h0, h1, l0, l1;
    h0.x = __float2bfloat16(v.x); h0.y = __float2bfloat16(v.y);
    h1.x = __float2bfloat16(v.z); h1.y = __float2bfloat16(v.w);
    l0.x = __float2bfloat16(v.x - __bfloat162float(h0.x));
    l0.y = __float2bfloat16(v.y - __bfloat162float(h0.y));
    l1.x = __float2bfloat16(v.z - __bfloat162float(h1.x));
    l1.y = __float2bfloat16(v.w - __bfloat162float(h1.y));
    ((__nv_bfloat162*)(hi + off))[2 * i]     = h0;
    ((__nv_bfloat162*)(hi + off))[2 * i + 1] = h1;
    ((__nv_bfloat162*)(lo + off))[2 * i]     = l0;
    ((__nv_bfloat162*)(lo + off))[2 * i + 1] = l1;
}

// ============================================================
// GEMM config (2-stage pipeline, pinned 2 CTAs/SM)
// ============================================================
#define KDIM 2048
#define TBK 32
#define NKIT (KDIM / TBK)
#define LDK 40
#define TILE_B (128 * LDK * 2)
#define STAGE_B (4 * TILE_B)
#define TC_SMEM (2 * STAGE_B)

// shared mainloop body as a macro to guarantee identical codegen
#define GEMM_MAINLOOP(Ahi_, Alo_, Bhi_, Blo_)                                          \
    const __nv_bfloat16* srcs[4] = { Ahi_, Alo_, Bhi_, Blo_ };                         \
    int l_tile[8], l_r[8], l_c[8];                                                     \
    _Pragma("unroll")                                                                  \
    for (int u = 0; u < 8; u++) {                                                      \
        int cid = u * 256 + tid;                                                       \
        l_tile[u] = cid >> 9;                                                          \
        int w = cid & 511;                                                             \
        l_r[u] = w >> 2;                                                               \
        l_c[u] = w & 3;                                                                \
    }                                                                                  \
    auto issue_stage = [&](int it, int stage) {                                        \
        uint32_t base = sb + stage * STAGE_B;                                          \
        int k0 = it * TBK;                                                             \
        _Pragma("unroll")                                                              \
        for (int u = 0; u < 8; u++) {                                                  \
            uint32_t dst = base + l_tile[u] * TILE_B + l_r[u] * (LDK * 2) + l_c[u] * 16;\
            const __nv_bfloat16* src = srcs[l_tile[u]] + (size_t)l_r[u] * KDIM + k0 + l_c[u] * 8;\
            cp16(dst, src);                                                            \
        }                                                                              \
        CP_COMMIT();                                                                   \
    };                                                                                 \
    float acc[2][8][4];                                                                \
    _Pragma("unroll")                                                                  \
    for (int i = 0; i < 2; i++)                                                        \
        _Pragma("unroll")                                                              \
        for (int j = 0; j < 8; j++)                                                    \
            _Pragma("unroll")                                                          \
            for (int q = 0; q < 4; q++) acc[i][j][q] = 0.f;                            \
    const int lrow = lane & 15;                                                        \
    const int lcol = (lane >> 4) * 8;                                                  \
    issue_stage(0, 0);                                                                 \
    for (int it = 0; it < NKIT; it++) {                                                \
        int cur = it & 1;                                                              \
        if (it + 1 < NKIT) { issue_stage(it + 1, cur ^ 1); CP_WAIT(1); }               \
        else { CP_WAIT(0); }                                                           \
        __syncthreads();                                                               \
        uint32_t base = sb + cur * STAGE_B;                                            \
        uint32_t aA_hi = base + 0 * TILE_B;                                            \
        uint32_t aA_lo = base + 1 * TILE_B;                                            \
        uint32_t aB_hi = base + 2 * TILE_B;                                            \
        uint32_t aB_lo = base + 3 * TILE_B;                                            \
        _Pragma("unroll")                                                              \
        for (int ks = 0; ks < 2; ks++) {                                               \
            const int kc = ks * 16 + lcol;                                             \
            uint32_t ah[2][4], al[2][4], bh[4][4], bl[4][4];                           \
            _Pragma("unroll")                                                          \
            for (int ma = 0; ma < 2; ma++) {                                           \
                uint32_t off = (wm + ma * 16 + lrow) * (LDK * 2) + kc * 2;             \
                ldsm_x4(ah[ma][0], ah[ma][1], ah[ma][2], ah[ma][3], aA_hi + off);      \
                ldsm_x4(al[ma][0], al[ma][1], al[ma][2], al[ma][3], aA_lo + off);      \
            }                                                                          \
            _Pragma("unroll")                                                          \
            for (int nb = 0; nb < 4; nb++) {                                           \
                uint32_t off = (wn + nb * 16 + lrow) * (LDK * 2) + kc * 2;             \
                ldsm_x4(bh[nb][0], bh[nb][1], bh[nb][2], bh[nb][3], aB_hi + off);      \
                ldsm_x4(bl[nb][0], bl[nb][1], bl[nb][2], bl[nb][3], aB_lo + off);      \
            }                                                                          \
            _Pragma("unroll")                                                          \
            for (int ma = 0; ma < 2; ma++)                                             \
                _Pragma("unroll")                                                      \
                for (int nb = 0; nb < 4; nb++) {                                       \
                    mma_bf16(acc[ma][nb * 2],     ah[ma], bh[nb][0], bh[nb][2]);       \
                    mma_bf16(acc[ma][nb * 2 + 1], ah[ma], bh[nb][1], bh[nb][3]);       \
                    mma_bf16(acc[ma][nb * 2],     ah[ma], bl[nb][0], bl[nb][2]);       \
                    mma_bf16(acc[ma][nb * 2 + 1], ah[ma], bl[nb][1], bl[nb][3]);       \
                    mma_bf16(acc[ma][nb * 2],     al[ma], bh[nb][0], bh[nb][2]);       \
                    mma_bf16(acc[ma][nb * 2 + 1], al[ma], bh[nb][1], bh[nb][3]);       \
                }                                                                      \
        }                                                                              \
        __syncthreads();                                                               \
    }

// ============================================================
// QKV GEMM, all three in one launch (blockIdx.z selects weight),
// bf16 pair out + fused RoPE for q,k. Pinned 2 CTAs/SM.
// ============================================================
__global__ __launch_bounds__(256, 2) void qkv_gemm(const __nv_bfloat16* __restrict__ Xhi,
                                                   const __nv_bfloat16* __restrict__ Xlo,
                                                   const __nv_bfloat16* __restrict__ Wh,
                                                   const __nv_bfloat16* __restrict__ Wl,
                                                   __nv_bfloat16* __restrict__ Qh, __nv_bfloat16* __restrict__ Ql,
                                                   __nv_bfloat16* __restrict__ Kh, __nv_bfloat16* __restrict__ Kl,
                                                   __nv_bfloat16* __restrict__ Vh, __nv_bfloat16* __restrict__ Vl,
                                                   const float* __restrict__ cs,
                                                   const float* __restrict__ sn) {
    extern __shared__ char smem[];
    const uint32_t sb = smem_to_u32(smem);
    const int tid = threadIdx.x;
    const int wid = tid >> 5, lane = tid & 31;
    const int m0 = blockIdx.y * 128;
    const int n0 = blockIdx.x * 128;
    const int z = blockIdx.z;
    const int wm = (wid & 3) * 32;
    const int wn = (wid >> 2) * 64;

    GEMM_MAINLOOP(Xhi + (size_t)m0 * KDIM, Xlo + (size_t)m0 * KDIM,
                  Wh + (size_t)z * DD + (size_t)n0 * KDIM,
                  Wl + (size_t)z * DD + (size_t)n0 * KDIM)

    __nv_bfloat16* Chi = (z == 0) ? Qh : (z == 1) ? Kh : Vh;
    __nv_bfloat16* Clo = (z == 0) ? Ql : (z == 1) ? Kl : Vl;
    const bool dorope = (z < 2);

    const int er = lane >> 2;
    const int ec = (lane & 3) * 2;
#pragma unroll
    for (int ma = 0; ma < 2; ma++)
#pragma unroll
        for (int na = 0; na < 8; na++) {
            int row = m0 + wm + ma * 16 + er;
            int col = n0 + wn + na * 8 + ec;
            float a0 = acc[ma][na][0], a1 = acc[ma][na][1];
            float a2 = acc[ma][na][2], a3 = acc[ma][na][3];
            if (dorope) {
                int p = (col & 127) >> 1;
                int s0 = row & (SS - 1), s1 = (row + 8) & (SS - 1);
                float c0 = cs[s0 * 64 + p], v0 = sn[s0 * 64 + p];
                float c1 = cs[s1 * 64 + p], v1 = sn[s1 * 64 + p];
                float t;
                t = a0 * c0 - a1 * v0; a1 = a0 * v0 + a1 * c0; a0 = t;
                t = a2 * c1 - a3 * v1; a3 = a2 * v1 + a3 * c1; a2 = t;
            }
            size_t i0 = (size_t)row * DIM + col;
            size_t i1 = (size_t)(row + 8) * DIM + col;
            uint32_t h, l;
            split2(a0, a1, h, l);
            *(uint32_t*)(Chi + i0) = h; *(uint32_t*)(Clo + i0) = l;
            split2(a2, a3, h, l);
            *(uint32_t*)(Chi + i1) = h; *(uint32_t*)(Clo + i1) = l;
        }
}

// ============================================================
// output projection (fp32 out), pinned 2 CTAs/SM
// ============================================================
__global__ __launch_bounds__(256, 2) void tc_gemm_f32(const __nv_bfloat16* __restrict__ Ahi,
                                                      const __nv_bfloat16* __restrict__ Alo,
                                                      const __nv_bfloat16* __restrict__ Bhi,
                                                      const __nv_bfloat16* __restrict__ Blo,
                                                      float* __restrict__ C) {
    extern __shared__ char smem[];
    const uint32_t sb = smem_to_u32(smem);
    const int tid = threadIdx.x;
    const int wid = tid >> 5, lane = tid & 31;
    const int m0 = blockIdx.y * 128;
    const int n0 = blockIdx.x * 128;
    const int wm = (wid & 3) * 32;
    const int wn = (wid >> 2) * 64;

    GEMM_MAINLOOP(Ahi + (size_t)m0 * KDIM, Alo + (size_t)m0 * KDIM,
                  Bhi + (size_t)n0 * KDIM, Blo + (size_t)n0 * KDIM)

    const int er = lane >> 2;
    const int ec = (lane & 3) * 2;
#pragma unroll
    for (int ma = 0; ma < 2; ma++)
#pragma unroll
        for (int na = 0; na < 8; na++) {
            int row = m0 + wm + ma * 16 + er;
            int col = n0 + wn + na * 8 + ec;
            float* p0 = C + (size_t)row * DIM + col;
            float* p1 = C + (size_t)(row + 8) * DIM + col;
            p0[0] = acc[ma][na][0]; p0[1] = acc[ma][na][1];
            p1[0] = acc[ma][na][2]; p1[1] = acc[ma][na][3];
        }
}

// ============================================================
// LoRA projection on tensor cores: C[128,32] per CTA,
// K=2048, BK=32 (80B rows, flash-rank-style stride), hi/lo 3-product.
// grid = (MROWS/128, 2 heads), 256 threads (8 warps x 16 rows).
// ============================================================
#define LBK 32
#define LNKIT (KDIM / LBK)
#define LXT (128 * 80)        // X tile bytes (hi or lo): 128 rows x 80B
#define LWT (32 * 80)         // W tile bytes
#define LSTAGE (2 * LXT + 2 * LWT)   // 25600
#define L_SMEM (2 * LSTAGE)          // 51200

__global__ __launch_bounds__(256) void lora_mma(const __nv_bfloat16* __restrict__ Xhi,
                                                const __nv_bfloat16* __restrict__ Xlo,
                                                const __nv_bfloat16* __restrict__ LWh,
                                                const __nv_bfloat16* __restrict__ LWl,
                                                __nv_bfloat16* __restrict__ Qh,
                                                __nv_bfloat16* __restrict__ Ql,
                                                __nv_bfloat16* __restrict__ Kh,
                                                __nv_bfloat16* __restrict__ Kl) {
    extern __shared__ char smem[];
    const uint32_t sb = smem_to_u32(smem);
    const int tid = threadIdx.x;
    const int wid = tid >> 5, lane = tid & 31;
    const int m0 = blockIdx.x * 128;
    const int head = blockIdx.y;
    const int wm = wid * 16;
    const int lrow = lane & 15, lcol = (lane >> 4) * 8;

    const __nv_bfloat16* xh = Xhi + (size_t)m0 * KDIM;
    const __nv_bfloat16* xl = Xlo + (size_t)m0 * KDIM;
    const __nv_bfloat16* wh = LWh + (size_t)head * (RANK * DIM);
    const __nv_bfloat16* wl = LWl + (size_t)head * (RANK * DIM);
    __nv_bfloat16* Ch = head ? Kh : Qh;
    __nv_bfloat16* Cl = head ? Kl : Ql;

    // per-stage chunk map: 1280 chunks of 16B, 5 per thread
    auto issue_stage = [&](int it, int stage) {
        uint32_t base = sb + stage * LSTAGE;
        int k0 = it * LBK;
#pragma unroll
        for (int u = 0; u < 5; u++) {
            int cid = u * 256 + tid;
            if (cid < 1024) {            // X chunks: buf(hi/lo), row 0..127, c 0..3
                int buf = cid >> 9, w = cid & 511;
                int row = w >> 2, c = w & 3;
                const __nv_bfloat16* src = (buf ? xl : xh) + (size_t)row * KDIM + k0 + c * 8;
                cp16(base + buf * LXT + row * 80 + c * 16, src);
            } else {                     // W chunks
                int w = cid - 1024;
                int buf = w >> 7, v = w & 127;
                int row = v >> 2, c = v & 3;
                const __nv_bfloat16* src = (buf ? wl : wh) + (size_t)row * KDIM + k0 + c * 8;
                cp16(base + 2 * LXT + buf * LWT + row * 80 + c * 16, src);
            }
        }
        CP_COMMIT();
    };

    float acc[4][4];
#pragma unroll
    for (int i = 0; i < 4; i++)
#pragma unroll
        for (int q = 0; q < 4; q++) acc[i][q] = 0.f;

    issue_stage(0, 0);

    for (int it = 0; it < LNKIT; it++) {
        int cur = it & 1;
        if (it + 1 < LNKIT) {
            issue_stage(it + 1, cur ^ 1);
            CP_WAIT(1);
        } else {
            CP_WAIT(0);
        }
        __syncthreads();

        uint32_t base = sb + cur * LSTAGE;
        uint32_t aXh = base, aXl = base + LXT;
        uint32_t aWh = base + 2 * LXT, aWl = aWh + LWT;

#pragma unroll
        for (int ks = 0; ks < 2; ks++) {
            const int kc = ks * 16 + lcol;
            uint32_t ah[4], al[4], bh[2][4], bl[2][4];
            {
                uint32_t off = (wm + lrow) * 80 + kc * 2;
                ldsm_x4(ah[0], ah[1], ah[2], ah[3], aXh + off);
                ldsm_x4(al[0], al[1], al[2], al[3], aXl + off);
            }
#pragma unroll
            for (int nb = 0; nb < 2; nb++) {
                uint32_t off = (nb * 16 + lrow) * 80 + kc * 2;
                ldsm_x4(bh[nb][0], bh[nb][1], bh[nb][2], bh[nb][3], aWh + off);
                ldsm_x4(bl[nb][0], bl[nb][1], bl[nb][2], bl[nb][3], aWl + off);
            }
#pragma unroll
            for (int nb = 0; nb < 2; nb++) {
                mma_bf16(acc[nb * 2],     ah, bh[nb][0], bh[nb][2]);
                mma_bf16(acc[nb * 2],     ah, bl[nb][0], bl[nb][2]);
                mma_bf16(acc[nb * 2],     al, bh[nb][0], bh[nb][2]);
                mma_bf16(acc[nb * 2 + 1], ah, bh[nb][1], bh[nb][3]);
                mma_bf16(acc[nb * 2 + 1], ah, bl[nb][1], bl[nb][3]);
                mma_bf16(acc[nb * 2 + 1], al, bh[nb][1], bh[nb][3]);
            }
        }
        __syncthreads();
    }

    const int er = lane >> 2;
    const int ec = (lane & 3) * 2;
#pragma unroll
    for (int na = 0; na < 4; na++) {
        int row = m0 + wm + er;
        int col = na * 8 + ec;
        size_t i0 = (size_t)row * RANK + col;
        size_t i1 = (size_t)(row + 8) * RANK + col;
        uint32_t h, l;
        split2(acc[na][0], acc[na][1], h, l);
        *(uint32_t*)(Ch + i0) = h; *(uint32_t*)(Cl + i0) = l;
        split2(acc[na][2], acc[na][3], h, l);
        *(uint32_t*)(Ch + i1) = h; *(uint32_t*)(Cl + i1) = l;
    }
}

// ============================================================
// Tensor-core flash attention (R12/R14 winner, unchanged)
// ============================================================
#define SQB 272
#define SRB 80
#define KTILE 17408
#define KSTG  (2 * KTILE)
#define HTILE 5120
#define HSTG  (2 * HTILE)
#define oQh 0
#define oQl 34816
#define oK  69632
#define oV  139264
#define oqh 174080
#define oql 184320
#define okh 194560
#define FSMEM 215040

__global__ __launch_bounds__(256) void flash_tc(
    const __nv_bfloat16* __restrict__ Qh_, const __nv_bfloat16* __restrict__ Ql_,
    const __nv_bfloat16* __restrict__ Kh_, const __nv_bfloat16* __restrict__ Kl_,
    const __nv_bfloat16* __restrict__ Vh_, const __nv_bfloat16* __restrict__ Vl_,
    const __nv_bfloat16* __restrict__ QHh_, const __nv_bfloat16* __restrict__ QHl_,
    const __nv_bfloat16* __restrict__ KHh_, const __nv_bfloat16* __restrict__ KHl_,
    __nv_bfloat16* __restrict__ Oh, __nv_bfloat16* __restrict__ Ol) {
    extern __shared__ char sm[];
    const uint32_t sb = smem_to_u32(sm);
    const int tid = threadIdx.x, lane = tid & 31, wid = tid >> 5;
    const int qt = gridDim.x - 1 - blockIdx.x;
    const int b = blockIdx.y >> 4, h = blockIdx.y & 15;
    const int q0 = qt * 128;
    const size_t rowbase = (size_t)b * SS;
    const int wm = wid * 16;
    const int lrow = lane & 15, lcol = (lane >> 4) * 8;
    const float SC2 = 0.08838834764831845f * 1.4426950408889634f;
    const float L2E = 1.4426950408889634f;

    auto issue_K = [&](int kt) {
        int nk0 = min(kt * 64, SS - 64);
        int stg = kt & 1;
        uint32_t bKh = sb + oK + stg * KSTG;
        uint32_t bKl = bKh + KTILE;
#pragma unroll
        for (int u = 0; u < 4; u++) {
            int cid = u * 256 + tid;
            int row = cid >> 4, col = cid & 15;
            size_t g = (rowbase + nk0 + row) * DIM + h * HD + col * 8;
            cp16(bKh + row * SQB + col * 16, Kh_ + g);
            cp16(bKl + row * SQB + col * 16, Kl_ + g);
        }
        uint32_t bkh = sb + okh + stg * HSTG;
        {
            int row = tid >> 2, col = tid & 3;
            size_t g = (rowbase + nk0 + row) * RANK + col * 8;
            cp16(bkh + row * SRB + col * 16, KHh_ + g);
            cp16(bkh + HTILE + row * SRB + col * 16, KHl_ + g);
        }
        CP_COMMIT();
    };
    auto issue_V = [&](int kt) {
        int nk0 = min(kt * 64, SS - 64);
#pragma unroll
        for (int u = 0; u < 4; u++) {
            int cid = u * 256 + tid;
            int row = cid >> 4, col = cid & 15;
            size_t g = (rowbase + nk0 + row) * DIM + h * HD + col * 8;
            cp16(sb + oV + row * SQB + col * 16, Vh_ + g);
            cp16(sb + oV + KTILE + row * SQB + col * 16, Vl_ + g);
        }
        CP_COMMIT();
    };

    {
#pragma unroll
        for (int u = 0; u < 8; u++) {
            int cid = u * 256 + tid;
            int row = cid >> 4, col = cid & 15;
            size_t g = (rowbase + q0 + row) * DIM + h * HD + col * 8;
            cp16(sb + oQh + row * SQB + col * 16, Qh_ + g);
            cp16(sb + oQl + row * SQB + col * 16, Ql_ + g);
        }
#pragma unroll
        for (int u = 0; u < 2; u++) {
            int cid = u * 256 + tid;
            int row = cid >> 2, col = cid & 3;
            size_t g = (rowbase + q0 + row) * RANK + col * 8;
            cp16(sb + oqh + row * SRB + col * 16, QHh_ + g);
            cp16(sb + oql + row * SRB + col * 16, QHl_ + g);
        }
        CP_COMMIT();
    }
    issue_K(0);
    issue_V(0);

    uint32_t qf[8][2][4];
    uint32_t qhf[2][2][4];
    CP_WAIT(2);
    __syncthreads();
#pragma unroll
    for (int ks = 0; ks < 8; ks++) {
        const int kc = ks * 16 + lcol;
        uint32_t off = (wm + lrow) * SQB + kc * 2;
        ldsm_x4(qf[ks][0][0], qf[ks][0][1], qf[ks][0][2], qf[ks][0][3], sb + oQh + off);
        ldsm_x4(qf[ks][1][0], qf[ks][1][1], qf[ks][1][2], qf[ks][1][3], sb + oQl + off);
    }
#pragma unroll
    for (int ks = 0; ks < 2; ks++) {
        const int kc = ks * 16 + lcol;
        uint32_t off = (wm + lrow) * SRB + kc * 2;
        ldsm_x4(qhf[ks][0][0], qhf[ks][0][1], qhf[ks][0][2], qhf[ks][0][3], sb + oqh + off);
        ldsm_x4(qhf[ks][1][0], qhf[ks][1][1], qhf[ks][1][2], qhf[ks][1][3], sb + oql + off);
    }

    float o[16][4];
#pragma unroll
    for (int i = 0; i < 16; i++)
#pragma unroll
        for (int e = 0; e < 4; e++) o[i][e] = 0.f;
    float m0 = -1e30f, m1 = -1e30f, l0 = 0.f, l1 = 0.f;

    const int nkt = q0 / 64 + 2;
    for (int kt = 0; kt < nkt; kt++) {
        const int k0 = kt * 64;
        const int kb = kt & 1;
        CP_WAIT(1);
        __syncthreads();
        issue_K(kt + 1);

        const bool skip = (k0 > q0 + wm + 15);
        float s[8][4];
        if (!skip) {
            const uint32_t bKh = sb + oK + kb * KSTG, bKl = bKh + KTILE;
            const uint32_t bkh = sb + okh + kb * HSTG, bkl = bkh + HTILE;

            float gg[8][4];
#pragma unroll
            for (int i = 0; i < 8; i++)
#pragma unroll
                for (int e = 0; e < 4; e++) gg[i][e] = 0.f;
#pragma unroll
            for (int ks = 0; ks < 2; ks++) {
#pragma unroll
                for (int nb = 0; nb < 4; nb++) {
                    uint32_t bh[4], bl[4];
                    uint32_t boff = (nb * 16 + lrow) * SRB + (ks * 16 + lcol) * 2;
                    ldsm_x4(bh[0], bh[1], bh[2], bh[3], bkh + boff);
                    ldsm_x4(bl[0], bl[1], bl[2], bl[3], bkl + boff);
                    mma_bf16(gg[nb * 2],     qhf[ks][0], bh[0], bh[2]);
                    mma_bf16(gg[nb * 2],     qhf[ks][0], bl[0], bl[2]);
                    mma_bf16(gg[nb * 2],     qhf[ks][1], bh[0], bh[2]);
                    mma_bf16(gg[nb * 2 + 1], qhf[ks][0], bh[1], bh[3]);
                    mma_bf16(gg[nb * 2 + 1], qhf[ks][0], bl[1], bl[3]);
                    mma_bf16(gg[nb * 2 + 1], qhf[ks][1], bh[1], bh[3]);
                }
            }
#pragma unroll
            for (int i = 0; i < 8; i++)
#pragma unroll
                for (int e = 0; e < 4; e++)
                    gg[i][e] = fast_rcp(1.f + fast_ex2(-L2E * gg[i][e]));

#pragma unroll
            for (int i = 0; i < 8; i++)
#pragma unroll
                for (int e = 0; e < 4; e++) s[i][e] = 0.f;
#pragma unroll
            for (int ks = 0; ks < 8; ks++) {
#pragma unroll
                for (int nb = 0; nb < 4; nb++) {
                    uint32_t bh[4], bl[4];
                    uint32_t boff = (nb * 16 + lrow) * SQB + (ks * 16 + lcol) * 2;
                    ldsm_x4(bh[0], bh[1], bh[2], bh[3], bKh + boff);
                    ldsm_x4(bl[0], bl[1], bl[2], bl[3], bKl + boff);
                    mma_bf16(s[nb * 2],     qf[ks][0], bh[0], bh[2]);
                    mma_bf16(s[nb * 2],     qf[ks][0], bl[0], bl[2]);
                    mma_bf16(s[nb * 2],     qf[ks][1], bh[0], bh[2]);
                    mma_bf16(s[nb * 2 + 1], qf[ks][0], bh[1], bh[3]);
                    mma_bf16(s[nb * 2 + 1], qf[ks][0], bl[1], bl[3]);
                    mma_bf16(s[nb * 2 + 1], qf[ks][1], bh[1], bh[3]);
                }
            }

            const int r0g = q0 + wm + (lane >> 2);
            if (k0 + 64 > q0 + wm) {
#pragma unroll
                for (int na = 0; na < 8; na++)
#pragma unroll
                    for (int e = 0; e < 4; e++) {
                        int key = k0 + na * 8 + (lane & 3) * 2 + (e & 1);
                        int row = r0g + (e >> 1) * 8;
                        s[na][e] = (key <= row) ? s[na][e] * SC2 : -1e30f;
                    }
            } else {
#pragma unroll
                for (int na = 0; na < 8; na++)
#pragma unroll
                    for (int e = 0; e < 4; e++) s[na][e] *= SC2;
            }

            float mx0 = -1e30f, mx1 = -1e30f;
#pragma unroll
            for (int na = 0; na < 8; na++) {
                mx0 = fmaxf(mx0, fmaxf(s[na][0], s[na][1]));
                mx1 = fmaxf(mx1, fmaxf(s[na][2], s[na][3]));
            }
            mx0 = fmaxf(mx0, __shfl_xor_sync(0xffffffffu, mx0, 1));
            mx0 = fmaxf(mx0, __shfl_xor_sync(0xffffffffu, mx0, 2));
            mx1 = fmaxf(mx1, __shfl_xor_sync(0xffffffffu, mx1, 1));
            mx1 = fmaxf(mx1, __shfl_xor_sync(0xffffffffu, mx1, 2));
            float mn0 = fmaxf(m0, mx0), mn1 = fmaxf(m1, mx1);
            float al0 = fast_ex2(m0 - mn0), al1 = fast_ex2(m1 - mn1);
            m0 = mn0; m1 = mn1;
            float rs0 = 0.f, rs1 = 0.f;
#pragma unroll
            for (int na = 0; na < 8; na++) {
                s[na][0] = fast_ex2(s[na][0] - m0); rs0 += s[na][0];
                s[na][1] = fast_ex2(s[na][1] - m0); rs0 += s[na][1];
                s[na][2] = fast_ex2(s[na][2] - m1); rs1 += s[na][2];
                s[na][3] = fast_ex2(s[na][3] - m1); rs1 += s[na][3];
            }
            rs0 += __shfl_xor_sync(0xffffffffu, rs0, 1);
            rs0 += __shfl_xor_sync(0xffffffffu, rs0, 2);
            rs1 += __shfl_xor_sync(0xffffffffu, rs1, 1);
            rs1 += __shfl_xor_sync(0xffffffffu, rs1, 2);
            l0 = l0 * al0 + rs0;
            l1 = l1 * al1 + rs1;
            if (al0 != 1.f || al1 != 1.f) {
#pragma unroll
                for (int na = 0; na < 16; na++) {
                    o[na][0] *= al0; o[na][1] *= al0;
                    o[na][2] *= al1; o[na][3] *= al1;
                }
            }
#pragma unroll
            for (int na = 0; na < 8; na++)
#pragma unroll
                for (int e = 0; e < 4; e++) s[na][e] *= gg[na][e];
        }

        CP_WAIT(1);
        __syncthreads();

        if (!skip) {
#pragma unroll
            for (int j = 0; j < 4; j++) {
                uint32_t wa[4], wl[4];
                split2(s[2 * j][0],     s[2 * j][1],     wa[0], wl[0]);
                split2(s[2 * j][2],     s[2 * j][3],     wa[1], wl[1]);
                split2(s[2 * j + 1][0], s[2 * j + 1][1], wa[2], wl[2]);
                split2(s[2 * j + 1][2], s[2 * j + 1][3], wa[3], wl[3]);
#pragma unroll
                for (int dp = 0; dp < 8; dp++) {
                    uint32_t vh[4], vl[4];
                    uint32_t voff = (j * 16 + lrow) * SQB + (dp * 16 + lcol) * 2;
                    ldsm_x4t(vh[0], vh[1], vh[2], vh[3], sb + oV + voff);
                    ldsm_x4t(vl[0], vl[1], vl[2], vl[3], sb + oV + KTILE + voff);
                    mma_bf16(o[dp * 2],     wa, vh[0], vh[1]);
                    mma_bf16(o[dp * 2],     wa, vl[0], vl[1]);
                    mma_bf16(o[dp * 2],     wl, vh[0], vh[1]);
                    mma_bf16(o[dp * 2 + 1], wa, vh[2], vh[3]);
                    mma_bf16(o[dp * 2 + 1], wa, vl[2], vl[3]);
                    mma_bf16(o[dp * 2 + 1], wl, vh[2], vh[3]);
                }
            }
        }
        __syncthreads();
        issue_V(kt + 1);
    }

    const float inv0 = fast_rcp(l0), inv1 = fast_rcp(l1);
    const int row0 = q0 + wm + (lane >> 2);
    size_t base0 = (rowbase + row0) * DIM + h * HD;
    size_t base1 = base0 + 8 * (size_t)DIM;
#pragma unroll
    for (int na = 0; na < 16; na++) {
        int d = na * 8 + (lane & 3) * 2;
        uint32_t hv, lv;
        split2(o[na][0] * inv0, o[na][1] * inv0, hv, lv);
        *(uint32_t*)(Oh + base0 + d) = hv;
        *(uint32_t*)(Ol + base0 + d) = lv;
        split2(o[na][2] * inv1, o[na][3] * inv1, hv, lv);
        *(uint32_t*)(Oh + base1 + d) = hv;
        *(uint32_t*)(Ol + base1 + d) = lv;
    }
}

// ============================================================
// launch
// ============================================================
extern "C" void kernel_launch(void* const* d_in, const int* in_sizes, int n_in,
                              void* d_out, int out_size) {
    const float* x    = (const float*)d_in[0];
    const float* fcos = (const float*)d_in[2];
    const float* fsin = (const float*)d_in[3];
    const float* wq   = (const float*)d_in[4];
    const float* wk   = (const float*)d_in[5];
    const float* wv   = (const float*)d_in[6];
    const float* wo   = (const float*)d_in[7];
    const float* waq  = (const float*)d_in[8];
    const float* wak  = (const float*)d_in[9];
    float* out = (float*)d_out;

    __nv_bfloat16 *gxh, *gxl, *gaoh, *gaol, *gwh, *gwl, *glwh, *glwl;
    __nv_bfloat16 *qbh, *qbl, *kbh, *kbl, *vbh, *vbl, *qhh, *qhl, *khh, *khl;
    cudaGetSymbolAddress((void**)&gxh, g_xh);
    cudaGetSymbolAddress((void**)&gxl, g_xl);
    cudaGetSymbolAddress((void**)&gaoh, g_aoh);
    cudaGetSymbolAddress((void**)&gaol, g_aol);
    cudaGetSymbolAddress((void**)&gwh, g_wh);
    cudaGetSymbolAddress((void**)&gwl, g_wl);
    cudaGetSymbolAddress((void**)&glwh, g_lwh);
    cudaGetSymbolAddress((void**)&glwl, g_lwl);
    cudaGetSymbolAddress((void**)&qbh, g_qbh);
    cudaGetSymbolAddress((void**)&qbl, g_qbl);
    cudaGetSymbolAddress((void**)&kbh, g_kbh);
    cudaGetSymbolAddress((void**)&kbl, g_kbl);
    cudaGetSymbolAddress((void**)&vbh, g_vbh);
    cudaGetSymbolAddress((void**)&vbl, g_vbl);
    cudaGetSymbolAddress((void**)&qhh, g_qhh);
    cudaGetSymbolAddress((void**)&qhl, g_qhl);
    cudaGetSymbolAddress((void**)&khh, g_khh);
    cudaGetSymbolAddress((void**)&khl, g_khl);

    cudaFuncSetAttribute(qkv_gemm, cudaFuncAttributeMaxDynamicSharedMemorySize, TC_SMEM);
    cudaFuncSetAttribute(tc_gemm_f32, cudaFuncAttributeMaxDynamicSharedMemorySize, TC_SMEM);
    cudaFuncSetAttribute(lora_mma, cudaFuncAttributeMaxDynamicSharedMemorySize, L_SMEM);
    cudaFuncSetAttribute(flash_tc, cudaFuncAttributeMaxDynamicSharedMemorySize, FSMEM);

    const int XB = MROWS * DIM / 4 / 256;
    const int WB = DIM * DIM / 4 / 256;
    const int LWB = RANK * DIM / 4 / 256;

    f32_to_bf16pair<<<XB, 256>>>(x, gxh, gxl);
    conv_w4<<<dim3(WB, 4), 256>>>(wq, wk, wv, wo, gwh, gwl);
    conv_lw<<<dim3(LWB, 2), 256>>>(waq, wak, glwh, glwl);

    qkv_gemm<<<dim3(DIM / 128, MROWS / 128, 3), 256, TC_SMEM>>>(
        gxh, gxl, gwh, gwl, qbh, qbl, kbh, kbl, vbh, vbl, fcos, fsin);
    lora_mma<<<dim3(MROWS / 128, 2), 256, L_SMEM>>>(gxh, gxl, glwh, glwl,
                                                    qhh, qhl, khh, khl);

    flash_tc<<<dim3(SS / 128, BB * NH), 256, FSMEM>>>(qbh, qbl, kbh, kbl, vbh, vbl,
                                                      qhh, qhl, khh, khl, gaoh, gaol);

    tc_gemm_f32<<<dim3(DIM / 128, MROWS / 128), 256, TC_SMEM>>>(
        gaoh, gaol, gwh + 3 * DD, gwl + 3 * DD, out);
}

// round 17
// speedup vs baseline: 1.3308x; 1.0913x over previous
#include <cuda_runtime.h>
#include <cuda_bf16.h>
#include <cstdint>

#define BB 2
#define SS 2048
#define DIM 2048
#define NH 16
#define HD 128
#define RANK 32
#define MROWS (BB*SS)
#define DD ((size_t)DIM*DIM)

// -------- scratch (device globals; no allocation allowed) --------
__device__ __nv_bfloat16 g_xh [MROWS*DIM];
__device__ __nv_bfloat16 g_xl [MROWS*DIM];
__device__ __nv_bfloat16 g_aoh[MROWS*DIM];
__device__ __nv_bfloat16 g_aol[MROWS*DIM];
__device__ __nv_bfloat16 g_wh [4][DIM*DIM];
__device__ __nv_bfloat16 g_wl [4][DIM*DIM];
__device__ __nv_bfloat16 g_qbh[MROWS*DIM];
__device__ __nv_bfloat16 g_qbl[MROWS*DIM];
__device__ __nv_bfloat16 g_kbh[MROWS*DIM];
__device__ __nv_bfloat16 g_kbl[MROWS*DIM];
__device__ __nv_bfloat16 g_vbh[MROWS*DIM];
__device__ __nv_bfloat16 g_vbl[MROWS*DIM];
__device__ __nv_bfloat16 g_qhh[MROWS*RANK];
__device__ __nv_bfloat16 g_qhl[MROWS*RANK];
__device__ __nv_bfloat16 g_khh[MROWS*RANK];
__device__ __nv_bfloat16 g_khl[MROWS*RANK];
__device__ __nv_bfloat16 g_lwh[2][RANK*DIM];
__device__ __nv_bfloat16 g_lwl[2][RANK*DIM];

__device__ __forceinline__ uint32_t smem_to_u32(const void* smem_ptr) {
    uint32_t addr;
    asm("{ .reg .u64 tmp; cvta.to.shared.u64 tmp, %1; cvt.u32.u64 %0, tmp; }"
        : "=r"(addr) : "l"(smem_ptr));
    return addr;
}
__device__ __forceinline__ void ldsm_x4(uint32_t& d0, uint32_t& d1, uint32_t& d2,
                                        uint32_t& d3, uint32_t addr) {
    asm volatile("ldmatrix.sync.aligned.m8n8.x4.shared.b16 {%0,%1,%2,%3}, [%4];"
                 : "=r"(d0), "=r"(d1), "=r"(d2), "=r"(d3) : "r"(addr));
}
__device__ __forceinline__ void ldsm_x4t(uint32_t& d0, uint32_t& d1, uint32_t& d2,
                                         uint32_t& d3, uint32_t addr) {
    asm volatile("ldmatrix.sync.aligned.m8n8.x4.trans.shared.b16 {%0,%1,%2,%3}, [%4];"
                 : "=r"(d0), "=r"(d1), "=r"(d2), "=r"(d3) : "r"(addr));
}
__device__ __forceinline__ void mma_bf16(float* c, const uint32_t* a,
                                         uint32_t b0, uint32_t b1) {
    asm volatile("mma.sync.aligned.m16n8k16.row.col.f32.bf16.bf16.f32 "
                 "{%0,%1,%2,%3}, {%4,%5,%6,%7}, {%8,%9}, {%0,%1,%2,%3};"
                 : "+f"(c[0]), "+f"(c[1]), "+f"(c[2]), "+f"(c[3])
                 : "r"(a[0]), "r"(a[1]), "r"(a[2]), "r"(a[3]), "r"(b0), "r"(b1));
}
__device__ __forceinline__ void cp16(uint32_t dst, const void* src) {
    asm volatile("cp.async.cg.shared.global [%0], [%1], 16;" :: "r"(dst), "l"(src));
}
#define CP_COMMIT()  asm volatile("cp.async.commit_group;" ::: "memory")
#define CP_WAIT(n)   asm volatile("cp.async.wait_group %0;" :: "n"(n) : "memory")

__device__ __forceinline__ float fast_rcp(float x) {
    float r; asm("rcp.approx.f32 %0, %1;" : "=f"(r) : "f"(x)); return r;
}
__device__ __forceinline__ float fast_ex2(float x) {
    float r; asm("ex2.approx.f32 %0, %1;" : "=f"(r) : "f"(x)); return r;
}

__device__ __forceinline__ void split2(float x, float y, uint32_t& hi, uint32_t& lo) {
    __nv_bfloat16 hx = __float2bfloat16(x), hy = __float2bfloat16(y);
    float rx = x - __bfloat162float(hx), ry = y - __bfloat162float(hy);
    __nv_bfloat162 H; H.x = hx; H.y = hy;
    __nv_bfloat162 L; L.x = __float2bfloat16(rx); L.y = __float2bfloat16(ry);
    hi = *(uint32_t*)&H; lo = *(uint32_t*)&L;
}

// ============================================================
// fp32 -> (bf16 hi, bf16 lo)
// ============================================================
__global__ __launch_bounds__(256) void f32_to_bf16pair(const float* __restrict__ in,
                                                       __nv_bfloat16* __restrict__ hi,
                                                       __nv_bfloat16* __restrict__ lo) {
    int i = blockIdx.x * 256 + threadIdx.x;
    float4 v = ((const float4*)in)[i];
    __nv_bfloat162 h0, h1, l0, l1;
    h0.x = __float2bfloat16(v.x); h0.y = __float2bfloat16(v.y);
    h1.x = __float2bfloat16(v.z); h1.y = __float2bfloat16(v.w);
    l0.x = __float2bfloat16(v.x - __bfloat162float(h0.x));
    l0.y = __float2bfloat16(v.y - __bfloat162float(h0.y));
    l1.x = __float2bfloat16(v.z - __bfloat162float(h1.x));
    l1.y = __float2bfloat16(v.w - __bfloat162float(h1.y));
    ((__nv_bfloat162*)hi)[2 * i]     = h0;
    ((__nv_bfloat162*)hi)[2 * i + 1] = h1;
    ((__nv_bfloat162*)lo)[2 * i]     = l0;
    ((__nv_bfloat162*)lo)[2 * i + 1] = l1;
}

// all 4 weights in one launch (gridDim.y = 4)
__global__ __launch_bounds__(256) void conv_w4(const float* __restrict__ w0,
                                               const float* __restrict__ w1,
                                               const float* __restrict__ w2,
                                               const float* __restrict__ w3,
                                               __nv_bfloat16* __restrict__ hi,
                                               __nv_bfloat16* __restrict__ lo) {
    int z = blockIdx.y;
    const float* in = (z == 0) ? w0 : (z == 1) ? w1 : (z == 2) ? w2 : w3;
    size_t off = (size_t)z * DD;
    int i = blockIdx.x * 256 + threadIdx.x;
    float4 v = ((const float4*)in)[i];
    __nv_bfloat162 h0, h1, l0, l1;
    h0.x = __float2bfloat16(v.x); h0.y = __float2bfloat16(v.y);
    h1.x = __float2bfloat16(v.z); h1.y = __float2bfloat16(v.w);
    l0.x = __float2bfloat16(v.x - __bfloat162float(h0.x));
    l0.y = __float2bfloat16(v.y - __bfloat162float(h0.y));
    l1.x = __float2bfloat16(v.z - __bfloat162float(h1.x));
    l1.y = __float2bfloat16(v.w - __bfloat162float(h1.y));
    ((__nv_bfloat162*)(hi + off))[2 * i]     = h0;
    ((__nv_bfloat162*)(hi + off))[2 * i + 1] = h1;
    ((__nv_bfloat162*)(lo + off))[2 * i]     = l0;
    ((__nv_bfloat162*)(lo + off))[2 * i + 1] = l1;
}

// lora weights (32x2048 each, gridDim.y = 2)
__global__ __launch_bounds__(256) void conv_lw(const float* __restrict__ wq,
                                               const float* __restrict__ wk,
                                               __nv_bfloat16* __restrict__ hi,
                                               __nv_bfloat16* __restrict__ lo) {
    int z = blockIdx.y;
    const float* in = z ? wk : wq;
    size_t off = (size_t)z * (RANK * DIM);
    int i = blockIdx.x * 256 + threadIdx.x;
    float4 v = ((const float4*)in)[i];
    __nv_bfloat162 h0, h1, l0, l1;
    h0.x = __float2bfloat16(v.x); h0.y = __float2bfloat16(v.y);
    h1.x = __float2bfloat16(v.z); h1.y = __float2bfloat16(v.w);
    l0.x = __float2bfloat16(v.x - __bfloat162float(h0.x));
    l0.y = __float2bfloat16(v.y - __bfloat162float(h0.y));
    l1.x = __float2bfloat16(v.z - __bfloat162float(h1.x));
    l1.y = __float2bfloat16(v.w - __bfloat162float(h1.y));
    ((__nv_bfloat162*)(hi + off))[2 * i]     = h0;
    ((__nv_bfloat162*)(hi + off))[2 * i + 1] = h1;
    ((__nv_bfloat162*)(lo + off))[2 * i]     = l0;
    ((__nv_bfloat162*)(lo + off))[2 * i + 1] = l1;
}

// ============================================================
// GEMM config (2-stage pipeline, pinned 2 CTAs/SM)
// ============================================================
#define KDIM 2048
#define TBK 32
#define NKIT (KDIM / TBK)
#define LDK 40
#define TILE_B (128 * LDK * 2)
#define STAGE_B (4 * TILE_B)
#define TC_SMEM (2 * STAGE_B)

#define GEMM_MAINLOOP(Ahi_, Alo_, Bhi_, Blo_)                                          \
    const __nv_bfloat16* srcs[4] = { Ahi_, Alo_, Bhi_, Blo_ };                         \
    int l_tile[8], l_r[8], l_c[8];                                                     \
    _Pragma("unroll")                                                                  \
    for (int u = 0; u < 8; u++) {                                                      \
        int cid = u * 256 + tid;                                                       \
        l_tile[u] = cid >> 9;                                                          \
        int w = cid & 511;                                                             \
        l_r[u] = w >> 2;                                                               \
        l_c[u] = w & 3;                                                                \
    }                                                                                  \
    auto issue_stage = [&](int it, int stage) {                                        \
        uint32_t base = sb + stage * STAGE_B;                                          \
        int k0 = it * TBK;                                                             \
        _Pragma("unroll")                                                              \
        for (int u = 0; u < 8; u++) {                                                  \
            uint32_t dst = base + l_tile[u] * TILE_B + l_r[u] * (LDK * 2) + l_c[u] * 16;\
            const __nv_bfloat16* src = srcs[l_tile[u]] + (size_t)l_r[u] * KDIM + k0 + l_c[u] * 8;\
            cp16(dst, src);                                                            \
        }                                                                              \
        CP_COMMIT();                                                                   \
    };                                                                                 \
    float acc[2][8][4];                                                                \
    _Pragma("unroll")                                                                  \
    for (int i = 0; i < 2; i++)                                                        \
        _Pragma("unroll")                                                              \
        for (int j = 0; j < 8; j++)                                                    \
            _Pragma("unroll")                                                          \
            for (int q = 0; q < 4; q++) acc[i][j][q] = 0.f;                            \
    const int lrow = lane & 15;                                                        \
    const int lcol = (lane >> 4) * 8;                                                  \
    issue_stage(0, 0);                                                                 \
    for (int it = 0; it < NKIT; it++) {                                                \
        int cur = it & 1;                                                              \
        if (it + 1 < NKIT) { issue_stage(it + 1, cur ^ 1); CP_WAIT(1); }               \
        else { CP_WAIT(0); }                                                           \
        __syncthreads();                                                               \
        uint32_t base = sb + cur * STAGE_B;                                            \
        uint32_t aA_hi = base + 0 * TILE_B;                                            \
        uint32_t aA_lo = base + 1 * TILE_B;                                            \
        uint32_t aB_hi = base + 2 * TILE_B;                                            \
        uint32_t aB_lo = base + 3 * TILE_B;                                            \
        _Pragma("unroll")                                                              \
        for (int ks = 0; ks < 2; ks++) {                                               \
            const int kc = ks * 16 + lcol;                                             \
            uint32_t ah[2][4], al[2][4], bh[4][4], bl[4][4];                           \
            _Pragma("unroll")                                                          \
            for (int ma = 0; ma < 2; ma++) {                                           \
                uint32_t off = (wm + ma * 16 + lrow) * (LDK * 2) + kc * 2;             \
                ldsm_x4(ah[ma][0], ah[ma][1], ah[ma][2], ah[ma][3], aA_hi + off);      \
                ldsm_x4(al[ma][0], al[ma][1], al[ma][2], al[ma][3], aA_lo + off);      \
            }                                                                          \
            _Pragma("unroll")                                                          \
            for (int nb = 0; nb < 4; nb++) {                                           \
                uint32_t off = (wn + nb * 16 + lrow) * (LDK * 2) + kc * 2;             \
                ldsm_x4(bh[nb][0], bh[nb][1], bh[nb][2], bh[nb][3], aB_hi + off);      \
                ldsm_x4(bl[nb][0], bl[nb][1], bl[nb][2], bl[nb][3], aB_lo + off);      \
            }                                                                          \
            _Pragma("unroll")                                                          \
            for (int ma = 0; ma < 2; ma++)                                             \
                _Pragma("unroll")                                                      \
                for (int nb = 0; nb < 4; nb++) {                                       \
                    mma_bf16(acc[ma][nb * 2],     ah[ma], bh[nb][0], bh[nb][2]);       \
                    mma_bf16(acc[ma][nb * 2 + 1], ah[ma], bh[nb][1], bh[nb][3]);       \
                    mma_bf16(acc[ma][nb * 2],     ah[ma], bl[nb][0], bl[nb][2]);       \
                    mma_bf16(acc[ma][nb * 2 + 1], ah[ma], bl[nb][1], bl[nb][3]);       \
                    mma_bf16(acc[ma][nb * 2],     al[ma], bh[nb][0], bh[nb][2]);       \
                    mma_bf16(acc[ma][nb * 2 + 1], al[ma], bh[nb][1], bh[nb][3]);       \
                }                                                                      \
        }                                                                              \
        __syncthreads();                                                               \
    }

// ============================================================
// QKV GEMM, all three in one launch, fused RoPE. 2 CTAs/SM.
// ============================================================
__global__ __launch_bounds__(256, 2) void qkv_gemm(const __nv_bfloat16* __restrict__ Xhi,
                                                   const __nv_bfloat16* __restrict__ Xlo,
                                                   const __nv_bfloat16* __restrict__ Wh,
                                                   const __nv_bfloat16* __restrict__ Wl,
                                                   __nv_bfloat16* __restrict__ Qh, __nv_bfloat16* __restrict__ Ql,
                                                   __nv_bfloat16* __restrict__ Kh, __nv_bfloat16* __restrict__ Kl,
                                                   __nv_bfloat16* __restrict__ Vh, __nv_bfloat16* __restrict__ Vl,
                                                   const float* __restrict__ cs,
                                                   const float* __restrict__ sn) {
    extern __shared__ char smem[];
    const uint32_t sb = smem_to_u32(smem);
    const int tid = threadIdx.x;
    const int wid = tid >> 5, lane = tid & 31;
    const int m0 = blockIdx.y * 128;
    const int n0 = blockIdx.x * 128;
    const int z = blockIdx.z;
    const int wm = (wid & 3) * 32;
    const int wn = (wid >> 2) * 64;

    GEMM_MAINLOOP(Xhi + (size_t)m0 * KDIM, Xlo + (size_t)m0 * KDIM,
                  Wh + (size_t)z * DD + (size_t)n0 * KDIM,
                  Wl + (size_t)z * DD + (size_t)n0 * KDIM)

    __nv_bfloat16* Chi = (z == 0) ? Qh : (z == 1) ? Kh : Vh;
    __nv_bfloat16* Clo = (z == 0) ? Ql : (z == 1) ? Kl : Vl;
    const bool dorope = (z < 2);

    const int er = lane >> 2;
    const int ec = (lane & 3) * 2;
#pragma unroll
    for (int ma = 0; ma < 2; ma++)
#pragma unroll
        for (int na = 0; na < 8; na++) {
            int row = m0 + wm + ma * 16 + er;
            int col = n0 + wn + na * 8 + ec;
            float a0 = acc[ma][na][0], a1 = acc[ma][na][1];
            float a2 = acc[ma][na][2], a3 = acc[ma][na][3];
            if (dorope) {
                int p = (col & 127) >> 1;
                int s0 = row & (SS - 1), s1 = (row + 8) & (SS - 1);
                float c0 = cs[s0 * 64 + p], v0 = sn[s0 * 64 + p];
                float c1 = cs[s1 * 64 + p], v1 = sn[s1 * 64 + p];
                float t;
                t = a0 * c0 - a1 * v0; a1 = a0 * v0 + a1 * c0; a0 = t;
                t = a2 * c1 - a3 * v1; a3 = a2 * v1 + a3 * c1; a2 = t;
            }
            size_t i0 = (size_t)row * DIM + col;
            size_t i1 = (size_t)(row + 8) * DIM + col;
            uint32_t h, l;
            split2(a0, a1, h, l);
            *(uint32_t*)(Chi + i0) = h; *(uint32_t*)(Clo + i0) = l;
            split2(a2, a3, h, l);
            *(uint32_t*)(Chi + i1) = h; *(uint32_t*)(Clo + i1) = l;
        }
}

// ============================================================
// output projection (fp32 out), m-offset for split launch. 2 CTAs/SM.
// ============================================================
__global__ __launch_bounds__(256, 2) void tc_gemm_f32(const __nv_bfloat16* __restrict__ Ahi,
                                                      const __nv_bfloat16* __restrict__ Alo,
                                                      const __nv_bfloat16* __restrict__ Bhi,
                                                      const __nv_bfloat16* __restrict__ Blo,
                                                      float* __restrict__ C, int myofs) {
    extern __shared__ char smem[];
    const uint32_t sb = smem_to_u32(smem);
    const int tid = threadIdx.x;
    const int wid = tid >> 5, lane = tid & 31;
    const int m0 = (blockIdx.y + myofs) * 128;
    const int n0 = blockIdx.x * 128;
    const int wm = (wid & 3) * 32;
    const int wn = (wid >> 2) * 64;

    GEMM_MAINLOOP(Ahi + (size_t)m0 * KDIM, Alo + (size_t)m0 * KDIM,
                  Bhi + (size_t)n0 * KDIM, Blo + (size_t)n0 * KDIM)

    const int er = lane >> 2;
    const int ec = (lane & 3) * 2;
#pragma unroll
    for (int ma = 0; ma < 2; ma++)
#pragma unroll
        for (int na = 0; na < 8; na++) {
            int row = m0 + wm + ma * 16 + er;
            int col = n0 + wn + na * 8 + ec;
            float* p0 = C + (size_t)row * DIM + col;
            float* p1 = C + (size_t)(row + 8) * DIM + col;
            p0[0] = acc[ma][na][0]; p0[1] = acc[ma][na][1];
            p1[0] = acc[ma][na][2]; p1[1] = acc[ma][na][3];
        }
}

// ============================================================
// LoRA projection on tensor cores (R16 winner, unchanged)
// ============================================================
#define LBK 32
#define LNKIT (KDIM / LBK)
#define LXT (128 * 80)
#define LWT (32 * 80)
#define LSTAGE (2 * LXT + 2 * LWT)
#define L_SMEM (2 * LSTAGE)

__global__ __launch_bounds__(256) void lora_mma(const __nv_bfloat16* __restrict__ Xhi,
                                                const __nv_bfloat16* __restrict__ Xlo,
                                                const __nv_bfloat16* __restrict__ LWh,
                                                const __nv_bfloat16* __restrict__ LWl,
                                                __nv_bfloat16* __restrict__ Qh,
                                                __nv_bfloat16* __restrict__ Ql,
                                                __nv_bfloat16* __restrict__ Kh,
                                                __nv_bfloat16* __restrict__ Kl) {
    extern __shared__ char smem[];
    const uint32_t sb = smem_to_u32(smem);
    const int tid = threadIdx.x;
    const int wid = tid >> 5, lane = tid & 31;
    const int m0 = blockIdx.x * 128;
    const int head = blockIdx.y;
    const int wm = wid * 16;
    const int lrow = lane & 15, lcol = (lane >> 4) * 8;

    const __nv_bfloat16* xh = Xhi + (size_t)m0 * KDIM;
    const __nv_bfloat16* xl = Xlo + (size_t)m0 * KDIM;
    const __nv_bfloat16* wh = LWh + (size_t)head * (RANK * DIM);
    const __nv_bfloat16* wl = LWl + (size_t)head * (RANK * DIM);
    __nv_bfloat16* Ch = head ? Kh : Qh;
    __nv_bfloat16* Cl = head ? Kl : Ql;

    auto issue_stage = [&](int it, int stage) {
        uint32_t base = sb + stage * LSTAGE;
        int k0 = it * LBK;
#pragma unroll
        for (int u = 0; u < 5; u++) {
            int cid = u * 256 + tid;
            if (cid < 1024) {
                int buf = cid >> 9, w = cid & 511;
                int row = w >> 2, c = w & 3;
                const __nv_bfloat16* src = (buf ? xl : xh) + (size_t)row * KDIM + k0 + c * 8;
                cp16(base + buf * LXT + row * 80 + c * 16, src);
            } else {
                int w = cid - 1024;
                int buf = w >> 7, v = w & 127;
                int row = v >> 2, c = v & 3;
                const __nv_bfloat16* src = (buf ? wl : wh) + (size_t)row * KDIM + k0 + c * 8;
                cp16(base + 2 * LXT + buf * LWT + row * 80 + c * 16, src);
            }
        }
        CP_COMMIT();
    };

    float acc[4][4];
#pragma unroll
    for (int i = 0; i < 4; i++)
#pragma unroll
        for (int q = 0; q < 4; q++) acc[i][q] = 0.f;

    issue_stage(0, 0);

    for (int it = 0; it < LNKIT; it++) {
        int cur = it & 1;
        if (it + 1 < LNKIT) {
            issue_stage(it + 1, cur ^ 1);
            CP_WAIT(1);
        } else {
            CP_WAIT(0);
        }
        __syncthreads();

        uint32_t base = sb + cur * LSTAGE;
        uint32_t aXh = base, aXl = base + LXT;
        uint32_t aWh = base + 2 * LXT, aWl = aWh + LWT;

#pragma unroll
        for (int ks = 0; ks < 2; ks++) {
            const int kc = ks * 16 + lcol;
            uint32_t ah[4], al[4], bh[2][4], bl[2][4];
            {
                uint32_t off = (wm + lrow) * 80 + kc * 2;
                ldsm_x4(ah[0], ah[1], ah[2], ah[3], aXh + off);
                ldsm_x4(al[0], al[1], al[2], al[3], aXl + off);
            }
#pragma unroll
            for (int nb = 0; nb < 2; nb++) {
                uint32_t off = (nb * 16 + lrow) * 80 + kc * 2;
                ldsm_x4(bh[nb][0], bh[nb][1], bh[nb][2], bh[nb][3], aWh + off);
                ldsm_x4(bl[nb][0], bl[nb][1], bl[nb][2], bl[nb][3], aWl + off);
            }
#pragma unroll
            for (int nb = 0; nb < 2; nb++) {
                mma_bf16(acc[nb * 2],     ah, bh[nb][0], bh[nb][2]);
                mma_bf16(acc[nb * 2],     ah, bl[nb][0], bl[nb][2]);
                mma_bf16(acc[nb * 2],     al, bh[nb][0], bh[nb][2]);
                mma_bf16(acc[nb * 2 + 1], ah, bh[nb][1], bh[nb][3]);
                mma_bf16(acc[nb * 2 + 1], ah, bl[nb][1], bl[nb][3]);
                mma_bf16(acc[nb * 2 + 1], al, bh[nb][1], bh[nb][3]);
            }
        }
        __syncthreads();
    }

    const int er = lane >> 2;
    const int ec = (lane & 3) * 2;
#pragma unroll
    for (int na = 0; na < 4; na++) {
        int row = m0 + wm + er;
        int col = na * 8 + ec;
        size_t i0 = (size_t)row * RANK + col;
        size_t i1 = (size_t)(row + 8) * RANK + col;
        uint32_t h, l;
        split2(acc[na][0], acc[na][1], h, l);
        *(uint32_t*)(Ch + i0) = h; *(uint32_t*)(Cl + i0) = l;
        split2(acc[na][2], acc[na][3], h, l);
        *(uint32_t*)(Ch + i1) = h; *(uint32_t*)(Cl + i1) = l;
    }
}

// ============================================================
// Tensor-core flash attention (R12/R14 winner), split by ybase
// ============================================================
#define SQB 272
#define SRB 80
#define KTILE 17408
#define KSTG  (2 * KTILE)
#define HTILE 5120
#define HSTG  (2 * HTILE)
#define oQh 0
#define oQl 34816
#define oK  69632
#define oV  139264
#define oqh 174080
#define oql 184320
#define okh 194560
#define FSMEM 215040

__global__ __launch_bounds__(256) void flash_tc(
    const __nv_bfloat16* __restrict__ Qh_, const __nv_bfloat16* __restrict__ Ql_,
    const __nv_bfloat16* __restrict__ Kh_, const __nv_bfloat16* __restrict__ Kl_,
    const __nv_bfloat16* __restrict__ Vh_, const __nv_bfloat16* __restrict__ Vl_,
    const __nv_bfloat16* __restrict__ QHh_, const __nv_bfloat16* __restrict__ QHl_,
    const __nv_bfloat16* __restrict__ KHh_, const __nv_bfloat16* __restrict__ KHl_,
    __nv_bfloat16* __restrict__ Oh, __nv_bfloat16* __restrict__ Ol, int ybase) {
    extern __shared__ char sm[];
    const uint32_t sb = smem_to_u32(sm);
    const int tid = threadIdx.x, lane = tid & 31, wid = tid >> 5;
    const int qt = gridDim.x - 1 - blockIdx.x;
    const int yy = blockIdx.y + ybase;
    const int b = yy >> 4, h = yy & 15;
    const int q0 = qt * 128;
    const size_t rowbase = (size_t)b * SS;
    const int wm = wid * 16;
    const int lrow = lane & 15, lcol = (lane >> 4) * 8;
    const float SC2 = 0.08838834764831845f * 1.4426950408889634f;
    const float L2E = 1.4426950408889634f;

    auto issue_K = [&](int kt) {
        int nk0 = min(kt * 64, SS - 64);
        int stg = kt & 1;
        uint32_t bKh = sb + oK + stg * KSTG;
        uint32_t bKl = bKh + KTILE;
#pragma unroll
        for (int u = 0; u < 4; u++) {
            int cid = u * 256 + tid;
            int row = cid >> 4, col = cid & 15;
            size_t g = (rowbase + nk0 + row) * DIM + h * HD + col * 8;
            cp16(bKh + row * SQB + col * 16, Kh_ + g);
            cp16(bKl + row * SQB + col * 16, Kl_ + g);
        }
        uint32_t bkh = sb + okh + stg * HSTG;
        {
            int row = tid >> 2, col = tid & 3;
            size_t g = (rowbase + nk0 + row) * RANK + col * 8;
            cp16(bkh + row * SRB + col * 16, KHh_ + g);
            cp16(bkh + HTILE + row * SRB + col * 16, KHl_ + g);
        }
        CP_COMMIT();
    };
    auto issue_V = [&](int kt) {
        int nk0 = min(kt * 64, SS - 64);
#pragma unroll
        for (int u = 0; u < 4; u++) {
            int cid = u * 256 + tid;
            int row = cid >> 4, col = cid & 15;
            size_t g = (rowbase + nk0 + row) * DIM + h * HD + col * 8;
            cp16(sb + oV + row * SQB + col * 16, Vh_ + g);
            cp16(sb + oV + KTILE + row * SQB + col * 16, Vl_ + g);
        }
        CP_COMMIT();
    };

    {
#pragma unroll
        for (int u = 0; u < 8; u++) {
            int cid = u * 256 + tid;
            int row = cid >> 4, col = cid & 15;
            size_t g = (rowbase + q0 + row) * DIM + h * HD + col * 8;
            cp16(sb + oQh + row * SQB + col * 16, Qh_ + g);
            cp16(sb + oQl + row * SQB + col * 16, Ql_ + g);
        }
#pragma unroll
        for (int u = 0; u < 2; u++) {
            int cid = u * 256 + tid;
            int row = cid >> 2, col = cid & 3;
            size_t g = (rowbase + q0 + row) * RANK + col * 8;
            cp16(sb + oqh + row * SRB + col * 16, QHh_ + g);
            cp16(sb + oql + row * SRB + col * 16, QHl_ + g);
        }
        CP_COMMIT();
    }
    issue_K(0);
    issue_V(0);

    uint32_t qf[8][2][4];
    uint32_t qhf[2][2][4];
    CP_WAIT(2);
    __syncthreads();
#pragma unroll
    for (int ks = 0; ks < 8; ks++) {
        const int kc = ks * 16 + lcol;
        uint32_t off = (wm + lrow) * SQB + kc * 2;
        ldsm_x4(qf[ks][0][0], qf[ks][0][1], qf[ks][0][2], qf[ks][0][3], sb + oQh + off);
        ldsm_x4(qf[ks][1][0], qf[ks][1][1], qf[ks][1][2], qf[ks][1][3], sb + oQl + off);
    }
#pragma unroll
    for (int ks = 0; ks < 2; ks++) {
        const int kc = ks * 16 + lcol;
        uint32_t off = (wm + lrow) * SRB + kc * 2;
        ldsm_x4(qhf[ks][0][0], qhf[ks][0][1], qhf[ks][0][2], qhf[ks][0][3], sb + oqh + off);
        ldsm_x4(qhf[ks][1][0], qhf[ks][1][1], qhf[ks][1][2], qhf[ks][1][3], sb + oql + off);
    }

    float o[16][4];
#pragma unroll
    for (int i = 0; i < 16; i++)
#pragma unroll
        for (int e = 0; e < 4; e++) o[i][e] = 0.f;
    float m0 = -1e30f, m1 = -1e30f, l0 = 0.f, l1 = 0.f;

    const int nkt = q0 / 64 + 2;
    for (int kt = 0; kt < nkt; kt++) {
        const int k0 = kt * 64;
        const int kb = kt & 1;
        CP_WAIT(1);
        __syncthreads();
        issue_K(kt + 1);

        const bool skip = (k0 > q0 + wm + 15);
        float s[8][4];
        if (!skip) {
            const uint32_t bKh = sb + oK + kb * KSTG, bKl = bKh + KTILE;
            const uint32_t bkh = sb + okh + kb * HSTG, bkl = bkh + HTILE;

            float gg[8][4];
#pragma unroll
            for (int i = 0; i < 8; i++)
#pragma unroll
                for (int e = 0; e < 4; e++) gg[i][e] = 0.f;
#pragma unroll
            for (int ks = 0; ks < 2; ks++) {
#pragma unroll
                for (int nb = 0; nb < 4; nb++) {
                    uint32_t bh[4], bl[4];
                    uint32_t boff = (nb * 16 + lrow) * SRB + (ks * 16 + lcol) * 2;
                    ldsm_x4(bh[0], bh[1], bh[2], bh[3], bkh + boff);
                    ldsm_x4(bl[0], bl[1], bl[2], bl[3], bkl + boff);
                    mma_bf16(gg[nb * 2],     qhf[ks][0], bh[0], bh[2]);
                    mma_bf16(gg[nb * 2],     qhf[ks][0], bl[0], bl[2]);
                    mma_bf16(gg[nb * 2],     qhf[ks][1], bh[0], bh[2]);
                    mma_bf16(gg[nb * 2 + 1], qhf[ks][0], bh[1], bh[3]);
                    mma_bf16(gg[nb * 2 + 1], qhf[ks][0], bl[1], bl[3]);
                    mma_bf16(gg[nb * 2 + 1], qhf[ks][1], bh[1], bh[3]);
                }
            }
#pragma unroll
            for (int i = 0; i < 8; i++)
#pragma unroll
                for (int e = 0; e < 4; e++)
                    gg[i][e] = fast_rcp(1.f + fast_ex2(-L2E * gg[i][e]));

#pragma unroll
            for (int i = 0; i < 8; i++)
#pragma unroll
                for (int e = 0; e < 4; e++) s[i][e] = 0.f;
#pragma unroll
            for (int ks = 0; ks < 8; ks++) {
#pragma unroll
                for (int nb = 0; nb < 4; nb++) {
                    uint32_t bh[4], bl[4];
                    uint32_t boff = (nb * 16 + lrow) * SQB + (ks * 16 + lcol) * 2;
                    ldsm_x4(bh[0], bh[1], bh[2], bh[3], bKh + boff);
                    ldsm_x4(bl[0], bl[1], bl[2], bl[3], bKl + boff);
                    mma_bf16(s[nb * 2],     qf[ks][0], bh[0], bh[2]);
                    mma_bf16(s[nb * 2],     qf[ks][0], bl[0], bl[2]);
                    mma_bf16(s[nb * 2],     qf[ks][1], bh[0], bh[2]);
                    mma_bf16(s[nb * 2 + 1], qf[ks][0], bh[1], bh[3]);
                    mma_bf16(s[nb * 2 + 1], qf[ks][0], bl[1], bl[3]);
                    mma_bf16(s[nb * 2 + 1], qf[ks][1], bh[1], bh[3]);
                }
            }

            const int r0g = q0 + wm + (lane >> 2);
            if (k0 + 64 > q0 + wm) {
#pragma unroll
                for (int na = 0; na < 8; na++)
#pragma unroll
                    for (int e = 0; e < 4; e++) {
                        int key = k0 + na * 8 + (lane & 3) * 2 + (e & 1);
                        int row = r0g + (e >> 1) * 8;
                        s[na][e] = (key <= row) ? s[na][e] * SC2 : -1e30f;
                    }
            } else {
#pragma unroll
                for (int na = 0; na < 8; na++)
#pragma unroll
                    for (int e = 0; e < 4; e++) s[na][e] *= SC2;
            }

            float mx0 = -1e30f, mx1 = -1e30f;
#pragma unroll
            for (int na = 0; na < 8; na++) {
                mx0 = fmaxf(mx0, fmaxf(s[na][0], s[na][1]));
                mx1 = fmaxf(mx1, fmaxf(s[na][2], s[na][3]));
            }
            mx0 = fmaxf(mx0, __shfl_xor_sync(0xffffffffu, mx0, 1));
            mx0 = fmaxf(mx0, __shfl_xor_sync(0xffffffffu, mx0, 2));
            mx1 = fmaxf(mx1, __shfl_xor_sync(0xffffffffu, mx1, 1));
            mx1 = fmaxf(mx1, __shfl_xor_sync(0xffffffffu, mx1, 2));
            float mn0 = fmaxf(m0, mx0), mn1 = fmaxf(m1, mx1);
            float al0 = fast_ex2(m0 - mn0), al1 = fast_ex2(m1 - mn1);
            m0 = mn0; m1 = mn1;
            float rs0 = 0.f, rs1 = 0.f;
#pragma unroll
            for (int na = 0; na < 8; na++) {
                s[na][0] = fast_ex2(s[na][0] - m0); rs0 += s[na][0];
                s[na][1] = fast_ex2(s[na][1] - m0); rs0 += s[na][1];
                s[na][2] = fast_ex2(s[na][2] - m1); rs1 += s[na][2];
                s[na][3] = fast_ex2(s[na][3] - m1); rs1 += s[na][3];
            }
            rs0 += __shfl_xor_sync(0xffffffffu, rs0, 1);
            rs0 += __shfl_xor_sync(0xffffffffu, rs0, 2);
            rs1 += __shfl_xor_sync(0xffffffffu, rs1, 1);
            rs1 += __shfl_xor_sync(0xffffffffu, rs1, 2);
            l0 = l0 * al0 + rs0;
            l1 = l1 * al1 + rs1;
            if (al0 != 1.f || al1 != 1.f) {
#pragma unroll
                for (int na = 0; na < 16; na++) {
                    o[na][0] *= al0; o[na][1] *= al0;
                    o[na][2] *= al1; o[na][3] *= al1;
                }
            }
#pragma unroll
            for (int na = 0; na < 8; na++)
#pragma unroll
                for (int e = 0; e < 4; e++) s[na][e] *= gg[na][e];
        }

        CP_WAIT(1);
        __syncthreads();

        if (!skip) {
#pragma unroll
            for (int j = 0; j < 4; j++) {
                uint32_t wa[4], wl[4];
                split2(s[2 * j][0],     s[2 * j][1],     wa[0], wl[0]);
                split2(s[2 * j][2],     s[2 * j][3],     wa[1], wl[1]);
                split2(s[2 * j + 1][0], s[2 * j + 1][1], wa[2], wl[2]);
                split2(s[2 * j + 1][2], s[2 * j + 1][3], wa[3], wl[3]);
#pragma unroll
                for (int dp = 0; dp < 8; dp++) {
                    uint32_t vh[4], vl[4];
                    uint32_t voff = (j * 16 + lrow) * SQB + (dp * 16 + lcol) * 2;
                    ldsm_x4t(vh[0], vh[1], vh[2], vh[3], sb + oV + voff);
                    ldsm_x4t(vl[0], vl[1], vl[2], vl[3], sb + oV + KTILE + voff);
                    mma_bf16(o[dp * 2],     wa, vh[0], vh[1]);
                    mma_bf16(o[dp * 2],     wa, vl[0], vl[1]);
                    mma_bf16(o[dp * 2],     wl, vh[0], vh[1]);
                    mma_bf16(o[dp * 2 + 1], wa, vh[2], vh[3]);
                    mma_bf16(o[dp * 2 + 1], wa, vl[2], vl[3]);
                    mma_bf16(o[dp * 2 + 1], wl, vh[2], vh[3]);
                }
            }
        }
        __syncthreads();
        issue_V(kt + 1);
    }

    const float inv0 = fast_rcp(l0), inv1 = fast_rcp(l1);
    const int row0 = q0 + wm + (lane >> 2);
    size_t base0 = (rowbase + row0) * DIM + h * HD;
    size_t base1 = base0 + 8 * (size_t)DIM;
#pragma unroll
    for (int na = 0; na < 16; na++) {
        int d = na * 8 + (lane & 3) * 2;
        uint32_t hv, lv;
        split2(o[na][0] * inv0, o[na][1] * inv0, hv, lv);
        *(uint32_t*)(Oh + base0 + d) = hv;
        *(uint32_t*)(Ol + base0 + d) = lv;
        split2(o[na][2] * inv1, o[na][3] * inv1, hv, lv);
        *(uint32_t*)(Oh + base1 + d) = hv;
        *(uint32_t*)(Ol + base1 + d) = lv;
    }
}

// ============================================================
// launch (stream-forked DAG; all deps expressed via events)
// ============================================================
extern "C" void kernel_launch(void* const* d_in, const int* in_sizes, int n_in,
                              void* d_out, int out_size) {
    const float* x    = (const float*)d_in[0];
    const float* fcos = (const float*)d_in[2];
    const float* fsin = (const float*)d_in[3];
    const float* wq   = (const float*)d_in[4];
    const float* wk   = (const float*)d_in[5];
    const float* wv   = (const float*)d_in[6];
    const float* wo   = (const float*)d_in[7];
    const float* waq  = (const float*)d_in[8];
    const float* wak  = (const float*)d_in[9];
    float* out = (float*)d_out;

    __nv_bfloat16 *gxh, *gxl, *gaoh, *gaol, *gwh, *gwl, *glwh, *glwl;
    __nv_bfloat16 *qbh, *qbl, *kbh, *kbl, *vbh, *vbl, *qhh, *qhl, *khh, *khl;
    cudaGetSymbolAddress((void**)&gxh, g_xh);
    cudaGetSymbolAddress((void**)&gxl, g_xl);
    cudaGetSymbolAddress((void**)&gaoh, g_aoh);
    cudaGetSymbolAddress((void**)&gaol, g_aol);
    cudaGetSymbolAddress((void**)&gwh, g_wh);
    cudaGetSymbolAddress((void**)&gwl, g_wl);
    cudaGetSymbolAddress((void**)&glwh, g_lwh);
    cudaGetSymbolAddress((void**)&glwl, g_lwl);
    cudaGetSymbolAddress((void**)&qbh, g_qbh);
    cudaGetSymbolAddress((void**)&qbl, g_qbl);
    cudaGetSymbolAddress((void**)&kbh, g_kbh);
    cudaGetSymbolAddress((void**)&kbl, g_kbl);
    cudaGetSymbolAddress((void**)&vbh, g_vbh);
    cudaGetSymbolAddress((void**)&vbl, g_vbl);
    cudaGetSymbolAddress((void**)&qhh, g_qhh);
    cudaGetSymbolAddress((void**)&qhl, g_qhl);
    cudaGetSymbolAddress((void**)&khh, g_khh);
    cudaGetSymbolAddress((void**)&khl, g_khl);

    cudaFuncSetAttribute(qkv_gemm, cudaFuncAttributeMaxDynamicSharedMemorySize, TC_SMEM);
    cudaFuncSetAttribute(tc_gemm_f32, cudaFuncAttributeMaxDynamicSharedMemorySize, TC_SMEM);
    cudaFuncSetAttribute(lora_mma, cudaFuncAttributeMaxDynamicSharedMemorySize, L_SMEM);
    cudaFuncSetAttribute(flash_tc, cudaFuncAttributeMaxDynamicSharedMemorySize, FSMEM);

    // one-time side streams/events (host resources, no device allocation;
    // per-call kernel work is identical every call)
    static cudaStream_t s2 = nullptr, s3 = nullptr;
    static cudaEvent_t eX = nullptr, eL = nullptr, eQ = nullptr, eO1 = nullptr;
    if (!s2) {
        cudaStreamCreateWithFlags(&s2, cudaStreamNonBlocking);
        cudaStreamCreateWithFlags(&s3, cudaStreamNonBlocking);
        cudaEventCreateWithFlags(&eX,  cudaEventDisableTiming);
        cudaEventCreateWithFlags(&eL,  cudaEventDisableTiming);
        cudaEventCreateWithFlags(&eQ,  cudaEventDisableTiming);
        cudaEventCreateWithFlags(&eO1, cudaEventDisableTiming);
    }

    const int XB = MROWS * DIM / 4 / 256;
    const int WB = DIM * DIM / 4 / 256;
    const int LWB = RANK * DIM / 4 / 256;

    // main stream: x conversion, then weights, then QKV
    f32_to_bf16pair<<<XB, 256>>>(x, gxh, gxl);
    cudaEventRecord(eX, 0);

    // side stream s2: lora weight conversion + lora projection (needs x conv)
    cudaStreamWaitEvent(s2, eX, 0);
    conv_lw<<<dim3(LWB, 2), 256, 0, s2>>>(waq, wak, glwh, glwl);
    lora_mma<<<dim3(MROWS / 128, 2), 256, L_SMEM, s2>>>(gxh, gxl, glwh, glwl,
                                                        qhh, qhl, khh, khl);
    cudaEventRecord(eL, s2);

    conv_w4<<<dim3(WB, 4), 256>>>(wq, wk, wv, wo, gwh, gwl);
    qkv_gemm<<<dim3(DIM / 128, MROWS / 128, 3), 256, TC_SMEM>>>(
        gxh, gxl, gwh, gwl, qbh, qbl, kbh, kbl, vbh, vbl, fcos, fsin);
    cudaEventRecord(eQ, 0);

    // batch 1 half on s3: flash(b=1) then out-proj rows [2048,4096)
    cudaStreamWaitEvent(s3, eQ, 0);
    cudaStreamWaitEvent(s3, eL, 0);
    flash_tc<<<dim3(SS / 128, 16), 256, FSMEM, s3>>>(qbh, qbl, kbh, kbl, vbh, vbl,
                                                     qhh, qhl, khh, khl, gaoh, gaol, 16);
    tc_gemm_f32<<<dim3(DIM / 128, 16), 256, TC_SMEM, s3>>>(
        gaoh, gaol, gwh + 3 * DD, gwl + 3 * DD, out, 16);
    cudaEventRecord(eO1, s3);

    // batch 0 half on main stream: flash(b=0) then out-proj rows [0,2048)
    cudaStreamWaitEvent(0, eL, 0);
    flash_tc<<<dim3(SS / 128, 16), 256, FSMEM>>>(qbh, qbl, kbh, kbl, vbh, vbl,
                                                 qhh, qhl, khh, khl, gaoh, gaol, 0);
    tc_gemm_f32<<<dim3(DIM / 128, 16), 256, TC_SMEM>>>(
        gaoh, gaol, gwh + 3 * DD, gwl + 3 * DD, out, 0);

    // rejoin
    cudaStreamWaitEvent(0, eO1, 0);
}